// round 4
// baseline (speedup 1.0000x reference)
#include <cuda_runtime.h>
#include <cuda_bf16.h>
#include <stdint.h>
#include <math.h>

#define BSZ 64
#define NN 512
#define DD 256
#define BIGC 1.0e9f

__device__ float g_eA[BSZ*NN*DD];
__device__ float g_eB[BSZ*NN*DD];
__device__ float g_nA[BSZ*NN];
__device__ float g_nB[BSZ*NN];
__device__ __nv_bfloat16 g_K[(size_t)BSZ*NN*NN];
__device__ float g_u[BSZ*NN];
__device__ float g_v[BSZ*NN];
__device__ int   g_cA[BSZ*NN];
__device__ int   g_cB[BSZ*NN];
__device__ double g_acc[3];

// ---- bf16 helpers ----
__device__ __forceinline__ uint32_t pack_bf2(float a, float b) {
    __nv_bfloat162 h = __floats2bfloat162_rn(a, b);
    return *reinterpret_cast<uint32_t*>(&h);
}
__device__ __forceinline__ void unpack_bf2(uint32_t u, float& a, float& b) {
    a = __uint_as_float(u << 16);
    b = __uint_as_float(u & 0xffff0000u);
}

__global__ void zero_acc_kernel() {
    if (threadIdx.x < 3) g_acc[threadIdx.x] = 0.0;
}

__global__ void class_argmax_kernel(const float* __restrict__ la,
                                    const float* __restrict__ lb) {
    int t = blockIdx.x * blockDim.x + threadIdx.x;
    if (t >= BSZ*NN) return;
    float4 a = ((const float4*)la)[t];
    int ba = 0; float bv = a.x;
    if (a.y > bv) { bv = a.y; ba = 1; }
    if (a.z > bv) { bv = a.z; ba = 2; }
    if (a.w > bv) { bv = a.w; ba = 3; }
    g_cA[t] = ba;
    float4 b = ((const float4*)lb)[t];
    int bb = 0; bv = b.x;
    if (b.y > bv) { bv = b.y; bb = 1; }
    if (b.z > bv) { bv = b.z; bb = 2; }
    if (b.w > bv) { bv = b.w; bb = 3; }
    g_cB[t] = bb;
}

__device__ __forceinline__ void ln_row(float v[8],
    const float4& g0, const float4& g1, const float4& e0, const float4& e1,
    float* o)
{
    float s = 0.f, sq = 0.f;
    #pragma unroll
    for (int j = 0; j < 8; j++) {
        v[j] = v[j] > 0.f ? v[j] : 0.01f * v[j];
        s += v[j]; sq += v[j]*v[j];
    }
    #pragma unroll
    for (int off = 16; off; off >>= 1) {
        s  += __shfl_xor_sync(0xffffffffu, s, off);
        sq += __shfl_xor_sync(0xffffffffu, sq, off);
    }
    float mean = s * (1.f/256.f);
    float var  = sq * (1.f/256.f) - mean*mean;
    float rstd = rsqrtf(var + 1e-5f);
    o[0] = (v[0]-mean)*rstd*g0.x + e0.x;
    o[1] = (v[1]-mean)*rstd*g0.y + e0.y;
    o[2] = (v[2]-mean)*rstd*g0.z + e0.z;
    o[3] = (v[3]-mean)*rstd*g0.w + e0.w;
    o[4] = (v[4]-mean)*rstd*g1.x + e1.x;
    o[5] = (v[5]-mean)*rstd*g1.y + e1.y;
    o[6] = (v[6]-mean)*rstd*g1.z + e1.z;
    o[7] = (v[7]-mean)*rstd*g1.w + e1.w;
}

// Fused 2-layer MLP+LN, double-buffered W/A tiles (1 barrier per K-tile).
#define EMBED_SMEM ((64*256 + 2*16*256 + 2*64*16) * 4)

__global__ __launch_bounds__(256, 2)
void embed_kernel(const float* __restrict__ xA, const float* __restrict__ xB,
                  const float* __restrict__ W1, const float* __restrict__ b1,
                  const float* __restrict__ g1, const float* __restrict__ be1,
                  const float* __restrict__ W2, const float* __restrict__ b2,
                  const float* __restrict__ g2, const float* __restrict__ be2)
{
    extern __shared__ float sm[];
    float* Hs = sm;                 // 64*256
    float* Ws = sm + 64*256;        // 2 * 16*256
    float* As = Ws + 2*16*256;      // 2 * 64*16

    const float* X  = blockIdx.y ? xB   : xA;
    float* E        = blockIdx.y ? g_eB : g_eA;
    float* NRM      = blockIdx.y ? g_nB : g_nA;

    const int tid  = threadIdx.x;
    const int lane = tid & 31;
    const int warp = tid >> 5;
    const int row0 = blockIdx.x * 64;
    const int wr   = warp * 8;
    const int c0   = lane * 4;
    const int c1   = 128 + lane * 4;
    const int rr   = tid >> 2;
    const int cq   = (tid & 3) << 2;

    float acc[8][8];
    #pragma unroll
    for (int r = 0; r < 8; r++)
        #pragma unroll
        for (int c = 0; c < 8; c++) acc[r][c] = 0.f;

    float4 wreg[4], areg;

    // ---------------- stage 1: h = LN(leaky(x@W1+b1)) ----------------
    areg = *(const float4*)(X + (size_t)(row0 + rr)*DD + cq);
    {
        const float4* Wv = (const float4*)(W1);
        #pragma unroll
        for (int i = 0; i < 4; i++) wreg[i] = Wv[tid + i*256];
    }
    *(float4*)(As + rr*16 + cq) = areg;
    {
        float4* Wd = (float4*)Ws;
        #pragma unroll
        for (int i = 0; i < 4; i++) Wd[tid + i*256] = wreg[i];
    }
    __syncthreads();

    for (int kt = 0; kt < 16; kt++) {
        const int cur = kt & 1, nxt = cur ^ 1;
        if (kt < 15) {
            areg = *(const float4*)(X + (size_t)(row0 + rr)*DD + (kt+1)*16 + cq);
            const float4* Wv = (const float4*)(W1 + (size_t)(kt+1)*16*DD);
            #pragma unroll
            for (int i = 0; i < 4; i++) wreg[i] = Wv[tid + i*256];
        }
        const float* Wc = Ws + cur*16*256;
        const float* Ac = As + cur*64*16;
        #pragma unroll
        for (int kk = 0; kk < 16; kk++) {
            float4 w0 = *(const float4*)(Wc + kk*256 + c0);
            float4 w1 = *(const float4*)(Wc + kk*256 + c1);
            #pragma unroll
            for (int r = 0; r < 8; r++) {
                float a = Ac[(wr + r)*16 + kk];
                acc[r][0] = fmaf(a, w0.x, acc[r][0]);
                acc[r][1] = fmaf(a, w0.y, acc[r][1]);
                acc[r][2] = fmaf(a, w0.z, acc[r][2]);
                acc[r][3] = fmaf(a, w0.w, acc[r][3]);
                acc[r][4] = fmaf(a, w1.x, acc[r][4]);
                acc[r][5] = fmaf(a, w1.y, acc[r][5]);
                acc[r][6] = fmaf(a, w1.z, acc[r][6]);
                acc[r][7] = fmaf(a, w1.w, acc[r][7]);
            }
        }
        if (kt < 15) {
            *(float4*)(As + nxt*64*16 + rr*16 + cq) = areg;
            float4* Wd = (float4*)(Ws + nxt*16*256);
            #pragma unroll
            for (int i = 0; i < 4; i++) Wd[tid + i*256] = wreg[i];
        }
        __syncthreads();
    }
    {
        float4 bv0 = *(const float4*)(b1 + c0), bv1 = *(const float4*)(b1 + c1);
        float4 gv0 = *(const float4*)(g1 + c0), gv1 = *(const float4*)(g1 + c1);
        float4 ev0 = *(const float4*)(be1 + c0), ev1 = *(const float4*)(be1 + c1);
        #pragma unroll
        for (int r = 0; r < 8; r++) {
            float v[8], o[8];
            v[0]=acc[r][0]+bv0.x; v[1]=acc[r][1]+bv0.y; v[2]=acc[r][2]+bv0.z; v[3]=acc[r][3]+bv0.w;
            v[4]=acc[r][4]+bv1.x; v[5]=acc[r][5]+bv1.y; v[6]=acc[r][6]+bv1.z; v[7]=acc[r][7]+bv1.w;
            ln_row(v, gv0, gv1, ev0, ev1, o);
            *(float4*)(Hs + (wr + r)*256 + c0) = make_float4(o[0],o[1],o[2],o[3]);
            *(float4*)(Hs + (wr + r)*256 + c1) = make_float4(o[4],o[5],o[6],o[7]);
        }
    }
    __syncthreads();
    #pragma unroll
    for (int r = 0; r < 8; r++)
        #pragma unroll
        for (int c = 0; c < 8; c++) acc[r][c] = 0.f;

    // ---------------- stage 2: e = LN(leaky(h@W2+b2)) ----------------
    {
        const float4* Wv = (const float4*)(W2);
        #pragma unroll
        for (int i = 0; i < 4; i++) wreg[i] = Wv[tid + i*256];
        float4* Wd = (float4*)Ws;
        #pragma unroll
        for (int i = 0; i < 4; i++) Wd[tid + i*256] = wreg[i];
    }
    __syncthreads();

    for (int kt = 0; kt < 16; kt++) {
        const int cur = kt & 1, nxt = cur ^ 1;
        if (kt < 15) {
            const float4* Wv = (const float4*)(W2 + (size_t)(kt+1)*16*DD);
            #pragma unroll
            for (int i = 0; i < 4; i++) wreg[i] = Wv[tid + i*256];
        }
        const float* Wc = Ws + cur*16*256;
        #pragma unroll
        for (int kk = 0; kk < 16; kk++) {
            float4 w0 = *(const float4*)(Wc + kk*256 + c0);
            float4 w1 = *(const float4*)(Wc + kk*256 + c1);
            #pragma unroll
            for (int r = 0; r < 8; r++) {
                float a = Hs[(wr + r)*256 + kt*16 + kk];
                acc[r][0] = fmaf(a, w0.x, acc[r][0]);
                acc[r][1] = fmaf(a, w0.y, acc[r][1]);
                acc[r][2] = fmaf(a, w0.z, acc[r][2]);
                acc[r][3] = fmaf(a, w0.w, acc[r][3]);
                acc[r][4] = fmaf(a, w1.x, acc[r][4]);
                acc[r][5] = fmaf(a, w1.y, acc[r][5]);
                acc[r][6] = fmaf(a, w1.z, acc[r][6]);
                acc[r][7] = fmaf(a, w1.w, acc[r][7]);
            }
        }
        if (kt < 15) {
            float4* Wd = (float4*)(Ws + nxt*16*256);
            #pragma unroll
            for (int i = 0; i < 4; i++) Wd[tid + i*256] = wreg[i];
        }
        __syncthreads();
    }
    {
        float4 bv0 = *(const float4*)(b2 + c0), bv1 = *(const float4*)(b2 + c1);
        float4 gv0 = *(const float4*)(g2 + c0), gv1 = *(const float4*)(g2 + c1);
        float4 ev0 = *(const float4*)(be2 + c0), ev1 = *(const float4*)(be2 + c1);
        #pragma unroll
        for (int r = 0; r < 8; r++) {
            float v[8], o[8];
            v[0]=acc[r][0]+bv0.x; v[1]=acc[r][1]+bv0.y; v[2]=acc[r][2]+bv0.z; v[3]=acc[r][3]+bv0.w;
            v[4]=acc[r][4]+bv1.x; v[5]=acc[r][5]+bv1.y; v[6]=acc[r][6]+bv1.z; v[7]=acc[r][7]+bv1.w;
            ln_row(v, gv0, gv1, ev0, ev1, o);
            float ns = o[0]*o[0]+o[1]*o[1]+o[2]*o[2]+o[3]*o[3]
                     + o[4]*o[4]+o[5]*o[5]+o[6]*o[6]+o[7]*o[7];
            #pragma unroll
            for (int off = 16; off; off >>= 1)
                ns += __shfl_xor_sync(0xffffffffu, ns, off);
            size_t grow = (size_t)(row0 + wr + r);
            *(float4*)(E + grow*DD + c0) = make_float4(o[0],o[1],o[2],o[3]);
            *(float4*)(E + grow*DD + c1) = make_float4(o[4],o[5],o[6],o[7]);
            if (lane == 0) NRM[grow] = ns;
        }
    }
}

// cdist + cost_class + in/out loss + K(bf16) = exp(-2*cost_class).
__global__ __launch_bounds__(256, 2)
void cost_kernel(const float* __restrict__ pa, const float* __restrict__ pb)
{
    __shared__ __align__(16) float Ast[2][16][132];
    __shared__ __align__(16) float Bst[2][16][132];
    __shared__ float redi[8], redo[8];

    const int b  = blockIdx.z;
    const int ti = blockIdx.y;
    const int tj = blockIdx.x;
    const int tid = threadIdx.x;
    const int ty = tid >> 4;
    const int tx = tid & 15;

    const float* Ab = g_eA + (size_t)b*NN*DD + (size_t)ti*128*DD;
    const float* Bb = g_eB + (size_t)b*NN*DD + (size_t)tj*128*DD;

    float acc[8][8];
    #pragma unroll
    for (int r = 0; r < 8; r++)
        #pragma unroll
        for (int c = 0; c < 8; c++) acc[r][c] = 0.f;

    float4 avr[2], bvr[2];
    #pragma unroll
    for (int s = 0; s < 2; s++) {
        int idx = tid + s*256;
        int row = idx >> 2, cq = (idx & 3) << 2;
        avr[s] = *(const float4*)(Ab + (size_t)row*DD + cq);
        bvr[s] = *(const float4*)(Bb + (size_t)row*DD + cq);
    }
    #pragma unroll
    for (int s = 0; s < 2; s++) {
        int idx = tid + s*256;
        int row = idx >> 2, cq = (idx & 3) << 2;
        Ast[0][cq+0][row]=avr[s].x; Ast[0][cq+1][row]=avr[s].y;
        Ast[0][cq+2][row]=avr[s].z; Ast[0][cq+3][row]=avr[s].w;
        Bst[0][cq+0][row]=bvr[s].x; Bst[0][cq+1][row]=bvr[s].y;
        Bst[0][cq+2][row]=bvr[s].z; Bst[0][cq+3][row]=bvr[s].w;
    }
    __syncthreads();

    for (int kt = 0; kt < 16; kt++) {
        const int cur = kt & 1, nxt = cur ^ 1;
        if (kt < 15) {
            #pragma unroll
            for (int s = 0; s < 2; s++) {
                int idx = tid + s*256;
                int row = idx >> 2, cq = (idx & 3) << 2;
                avr[s] = *(const float4*)(Ab + (size_t)row*DD + (kt+1)*16 + cq);
                bvr[s] = *(const float4*)(Bb + (size_t)row*DD + (kt+1)*16 + cq);
            }
        }
        #pragma unroll
        for (int kk = 0; kk < 16; kk++) {
            float4 a0 = *(const float4*)(&Ast[cur][kk][ty*4]);
            float4 a1 = *(const float4*)(&Ast[cur][kk][64 + ty*4]);
            float4 b0 = *(const float4*)(&Bst[cur][kk][tx*4]);
            float4 b1 = *(const float4*)(&Bst[cur][kk][64 + tx*4]);
            float ar[8] = {a0.x,a0.y,a0.z,a0.w,a1.x,a1.y,a1.z,a1.w};
            float br[8] = {b0.x,b0.y,b0.z,b0.w,b1.x,b1.y,b1.z,b1.w};
            #pragma unroll
            for (int r = 0; r < 8; r++)
                #pragma unroll
                for (int c = 0; c < 8; c++)
                    acc[r][c] = fmaf(ar[r], br[c], acc[r][c]);
        }
        if (kt < 15) {
            #pragma unroll
            for (int s = 0; s < 2; s++) {
                int idx = tid + s*256;
                int row = idx >> 2, cq = (idx & 3) << 2;
                Ast[nxt][cq+0][row]=avr[s].x; Ast[nxt][cq+1][row]=avr[s].y;
                Ast[nxt][cq+2][row]=avr[s].z; Ast[nxt][cq+3][row]=avr[s].w;
                Bst[nxt][cq+0][row]=bvr[s].x; Bst[nxt][cq+1][row]=bvr[s].y;
                Bst[nxt][cq+2][row]=bvr[s].z; Bst[nxt][cq+3][row]=bvr[s].w;
            }
        }
        __syncthreads();
    }

    float ni[8], pav[8]; int cai[8];
    float njv[8], pbv[8]; int cbj[8];
    #pragma unroll
    for (int r = 0; r < 8; r++) {
        int il = ti*128 + ((r < 4) ? ty*4 + r : 64 + ty*4 + (r-4));
        int gi = b*NN + il;
        ni[r] = g_nA[gi]; pav[r] = pa[gi]; cai[r] = g_cA[gi];
    }
    #pragma unroll
    for (int c = 0; c < 8; c++) {
        int jl = tj*128 + ((c < 4) ? tx*4 + c : 64 + tx*4 + (c-4));
        int gj = b*NN + jl;
        njv[c] = g_nB[gj]; pbv[c] = pb[gj]; cbj[c] = g_cB[gj];
    }

    float sin = 0.f, sout = 0.f;
    #pragma unroll
    for (int r = 0; r < 8; r++) {
        int il = ti*128 + ((r < 4) ? ty*4 + r : 64 + ty*4 + (r-4));
        size_t rowb = ((size_t)(b*NN + il)) * NN;
        #pragma unroll
        for (int cg = 0; cg < 2; cg++) {
            float kv[4];
            #pragma unroll
            for (int c4 = 0; c4 < 4; c4++) {
                int c = cg*4 + c4;
                float sq   = ni[r] + njv[c] - 2.f*acc[r][c];
                float cost = sqrtf(fmaxf(sq, 0.f));
                float pm   = pav[r]*pbv[c];
                float cc   = cost + (BIGC - BIGC*pm);
                float w    = cc * pm;
                if (cai[r] == cbj[c]) sin += w; else sout += w;
                kv[c4] = __expf(-2.f*cc);
            }
            uint2 pk;
            pk.x = pack_bf2(kv[0], kv[1]);
            pk.y = pack_bf2(kv[2], kv[3]);
            *(uint2*)(g_K + rowb + tj*128 + cg*64 + tx*4) = pk;
        }
    }
    #pragma unroll
    for (int off = 16; off; off >>= 1) {
        sin  += __shfl_xor_sync(0xffffffffu, sin,  off);
        sout += __shfl_xor_sync(0xffffffffu, sout, off);
    }
    int lane = tid & 31, warp = tid >> 5;
    if (lane == 0) { redi[warp] = sin; redo[warp] = sout; }
    __syncthreads();
    if (tid == 0) {
        float a = 0.f, o2 = 0.f;
        #pragma unroll
        for (int w = 0; w < 8; w++) { a += redi[w]; o2 += redo[w]; }
        atomicAdd(&g_acc[0], (double)a);
        atomicAdd(&g_acc[1], (double)o2);
    }
}

// Sinkhorn, 1 CTA per batch, K (bf16) resident in L2.
__global__ __launch_bounds__(512)
void sinkhorn_kernel()
{
    __shared__ __align__(16) float su[NN];
    __shared__ __align__(16) float sv[NN];
    __shared__ __align__(16) float part[4][NN];

    const int b = blockIdx.x;
    const __nv_bfloat16* Kb = g_K + (size_t)b*NN*NN;
    const int tid  = threadIdx.x;
    const int lane = tid & 31;
    const int warp = tid >> 5;
    const int grp  = tid >> 7;
    const int jc   = (tid & 127) * 4;

    su[tid] = 1.f/512.f;
    __syncthreads();

    for (int it = 0; it < 10; it++) {
        // v = b / (K^T u)
        float a0 = 0.f, a1 = 0.f, a2 = 0.f, a3 = 0.f;
        const int i0 = grp * 128;
        const uint2* K2 = (const uint2*)Kb;
        #pragma unroll 4
        for (int i = 0; i < 128; i++) {
            uint2 kq = K2[(((size_t)(i0 + i))*NN + jc) >> 2];
            float k0,k1,k2,k3;
            unpack_bf2(kq.x, k0, k1);
            unpack_bf2(kq.y, k2, k3);
            float ui = su[i0 + i];
            a0 = fmaf(k0, ui, a0);
            a1 = fmaf(k1, ui, a1);
            a2 = fmaf(k2, ui, a2);
            a3 = fmaf(k3, ui, a3);
        }
        *(float4*)(&part[grp][jc]) = make_float4(a0,a1,a2,a3);
        __syncthreads();
        {
            float y = part[0][tid] + part[1][tid] + part[2][tid] + part[3][tid];
            sv[tid] = (1.f/512.f) / y;
        }
        __syncthreads();
        // u = a / (K v), warp per row; lane owns cols lane*16..+15
        for (int rr = 0; rr < 32; rr++) {
            int i = warp*32 + rr;
            const uint4* kr = (const uint4*)(Kb + (size_t)i*NN);
            uint4 q0 = kr[lane*2];
            uint4 q1 = kr[lane*2 + 1];
            float s = 0.f;
            float k0,k1;
            float4 vv;
            vv = *(const float4*)(sv + lane*16 + 0);
            unpack_bf2(q0.x, k0, k1); s = fmaf(k0, vv.x, s); s = fmaf(k1, vv.y, s);
            unpack_bf2(q0.y, k0, k1); s = fmaf(k0, vv.z, s); s = fmaf(k1, vv.w, s);
            vv = *(const float4*)(sv + lane*16 + 4);
            unpack_bf2(q0.z, k0, k1); s = fmaf(k0, vv.x, s); s = fmaf(k1, vv.y, s);
            unpack_bf2(q0.w, k0, k1); s = fmaf(k0, vv.z, s); s = fmaf(k1, vv.w, s);
            vv = *(const float4*)(sv + lane*16 + 8);
            unpack_bf2(q1.x, k0, k1); s = fmaf(k0, vv.x, s); s = fmaf(k1, vv.y, s);
            unpack_bf2(q1.y, k0, k1); s = fmaf(k0, vv.z, s); s = fmaf(k1, vv.w, s);
            vv = *(const float4*)(sv + lane*16 + 12);
            unpack_bf2(q1.z, k0, k1); s = fmaf(k0, vv.x, s); s = fmaf(k1, vv.y, s);
            unpack_bf2(q1.w, k0, k1); s = fmaf(k0, vv.z, s); s = fmaf(k1, vv.w, s);
            #pragma unroll
            for (int off = 16; off; off >>= 1)
                s += __shfl_xor_sync(0xffffffffu, s, off);
            if (lane == 0) su[i] = (1.f/512.f) / s;
        }
        __syncthreads();
    }
    g_u[b*NN + tid] = su[tid];
    g_v[b*NN + tid] = sv[tid];
}

__global__ void sup_kernel(const float* __restrict__ rel,
                           const float* __restrict__ pa)
{
    __shared__ float red[8];
    const size_t total8 = (size_t)BSZ*NN*NN/8;
    float lacc = 0.f;
    for (size_t idx = (size_t)blockIdx.x*blockDim.x + threadIdx.x; idx < total8;
         idx += (size_t)gridDim.x*blockDim.x) {
        size_t e = idx * 8;
        int b = (int)(e >> 18);
        int i = (int)((e >> 9) & 511);
        int j = (int)(e & 511);
        uint4 kq = ((const uint4*)g_K)[idx];
        float kf[8];
        unpack_bf2(kq.x, kf[0], kf[1]);
        unpack_bf2(kq.y, kf[2], kf[3]);
        unpack_bf2(kq.z, kf[4], kf[5]);
        unpack_bf2(kq.w, kf[6], kf[7]);
        float4 rv0 = ((const float4*)rel)[idx*2];
        float4 rv1 = ((const float4*)rel)[idx*2 + 1];
        float ui  = g_u[b*NN + i] * 512.f;
        float pai = pa[b*NN + i];
        float4 vv0 = *(const float4*)(g_v + b*NN + j);
        float4 vv1 = *(const float4*)(g_v + b*NN + j + 4);
        float d0 = ui*kf[0]*vv0.x - rv0.x;
        float d1 = ui*kf[1]*vv0.y - rv0.y;
        float d2 = ui*kf[2]*vv0.z - rv0.z;
        float d3 = ui*kf[3]*vv0.w - rv0.w;
        float d4 = ui*kf[4]*vv1.x - rv1.x;
        float d5 = ui*kf[5]*vv1.y - rv1.y;
        float d6 = ui*kf[6]*vv1.z - rv1.z;
        float d7 = ui*kf[7]*vv1.w - rv1.w;
        lacc += pai * (d0*d0 + d1*d1 + d2*d2 + d3*d3
                     + d4*d4 + d5*d5 + d6*d6 + d7*d7);
    }
    #pragma unroll
    for (int off = 16; off; off >>= 1)
        lacc += __shfl_xor_sync(0xffffffffu, lacc, off);
    int lane = threadIdx.x & 31, warp = threadIdx.x >> 5;
    if (lane == 0) red[warp] = lacc;
    __syncthreads();
    if (threadIdx.x == 0) {
        float s = 0.f;
        #pragma unroll
        for (int w = 0; w < 8; w++) s += red[w];
        atomicAdd(&g_acc[2], (double)s);
    }
}

__global__ void finalize_kernel(const float* __restrict__ pa, float* __restrict__ out)
{
    __shared__ float red[256];
    float s = 0.f;
    for (int i = threadIdx.x; i < BSZ*NN; i += 256) s += pa[i];
    red[threadIdx.x] = s;
    __syncthreads();
    for (int off = 128; off; off >>= 1) {
        if (threadIdx.x < off) red[threadIdx.x] += red[threadIdx.x + off];
        __syncthreads();
    }
    if (threadIdx.x == 0) {
        double M = (double)BSZ * (double)NN * (double)NN;
        out[0] = (float)(g_acc[0]/M - g_acc[1]/M + 10.0*(g_acc[2]/(double)red[0]));
    }
}

extern "C" void kernel_launch(void* const* d_in, const int* in_sizes, int n_in,
                              void* d_out, int out_size)
{
    const float* la  = (const float*)d_in[0];
    const float* lb  = (const float*)d_in[1];
    const float* xA  = (const float*)d_in[2];
    const float* xB  = (const float*)d_in[3];
    const float* rel = (const float*)d_in[4];
    const float* pa  = (const float*)d_in[5];
    const float* pb  = (const float*)d_in[6];
    const float* W1  = (const float*)d_in[7];
    const float* b1  = (const float*)d_in[8];
    const float* g1  = (const float*)d_in[9];
    const float* be1 = (const float*)d_in[10];
    const float* W2  = (const float*)d_in[11];
    const float* b2  = (const float*)d_in[12];
    const float* g2  = (const float*)d_in[13];
    const float* be2 = (const float*)d_in[14];
    float* out = (float*)d_out;

    cudaFuncSetAttribute(embed_kernel,
                         cudaFuncAttributeMaxDynamicSharedMemorySize, EMBED_SMEM);

    zero_acc_kernel<<<1, 32>>>();
    class_argmax_kernel<<<(BSZ*NN + 255)/256, 256>>>(la, lb);
    embed_kernel<<<dim3(BSZ*NN/64, 2), 256, EMBED_SMEM>>>(
        xA, xB, W1, b1, g1, be1, W2, b2, g2, be2);
    cost_kernel<<<dim3(4, 4, BSZ), 256>>>(pa, pb);
    sinkhorn_kernel<<<BSZ, 512>>>();
    sup_kernel<<<2048, 256>>>(rel, pa);
    finalize_kernel<<<1, 256>>>(pa, out);
}

// round 5
// speedup vs baseline: 1.1635x; 1.1635x over previous
#include <cuda_runtime.h>
#include <cuda_bf16.h>
#include <stdint.h>
#include <math.h>

#define BSZ 64
#define NN 512
#define DD 256
#define BIGC 1.0e9f

__device__ float g_eA[BSZ*NN*DD];
__device__ float g_eB[BSZ*NN*DD];
__device__ float g_nA[BSZ*NN];
__device__ float g_nB[BSZ*NN];
__device__ __nv_bfloat16 g_K[(size_t)BSZ*NN*NN];
__device__ float g_u[BSZ*NN];
__device__ float g_v[BSZ*NN];
__device__ int   g_cA[BSZ*NN];
__device__ int   g_cB[BSZ*NN];
__device__ double g_acc[3];

// ---- bf16 helpers ----
__device__ __forceinline__ uint32_t pack_bf2(float a, float b) {
    __nv_bfloat162 h = __floats2bfloat162_rn(a, b);
    return *reinterpret_cast<uint32_t*>(&h);
}
__device__ __forceinline__ void unpack_bf2(uint32_t u, float& a, float& b) {
    a = __uint_as_float(u << 16);
    b = __uint_as_float(u & 0xffff0000u);
}

__global__ void zero_acc_kernel() {
    if (threadIdx.x < 3) g_acc[threadIdx.x] = 0.0;
}

__global__ void class_argmax_kernel(const float* __restrict__ la,
                                    const float* __restrict__ lb) {
    int t = blockIdx.x * blockDim.x + threadIdx.x;
    if (t >= BSZ*NN) return;
    float4 a = ((const float4*)la)[t];
    int ba = 0; float bv = a.x;
    if (a.y > bv) { bv = a.y; ba = 1; }
    if (a.z > bv) { bv = a.z; ba = 2; }
    if (a.w > bv) { bv = a.w; ba = 3; }
    g_cA[t] = ba;
    float4 b = ((const float4*)lb)[t];
    int bb = 0; bv = b.x;
    if (b.y > bv) { bv = b.y; bb = 1; }
    if (b.z > bv) { bv = b.z; bb = 2; }
    if (b.w > bv) { bv = b.w; bb = 3; }
    g_cB[t] = bb;
}

__device__ __forceinline__ void ln_row(float v[8],
    const float4& g0, const float4& g1, const float4& e0, const float4& e1,
    float* o)
{
    float s = 0.f, sq = 0.f;
    #pragma unroll
    for (int j = 0; j < 8; j++) {
        v[j] = v[j] > 0.f ? v[j] : 0.01f * v[j];
        s += v[j]; sq += v[j]*v[j];
    }
    #pragma unroll
    for (int off = 16; off; off >>= 1) {
        s  += __shfl_xor_sync(0xffffffffu, s, off);
        sq += __shfl_xor_sync(0xffffffffu, sq, off);
    }
    float mean = s * (1.f/256.f);
    float var  = sq * (1.f/256.f) - mean*mean;
    float rstd = rsqrtf(var + 1e-5f);
    o[0] = (v[0]-mean)*rstd*g0.x + e0.x;
    o[1] = (v[1]-mean)*rstd*g0.y + e0.y;
    o[2] = (v[2]-mean)*rstd*g0.z + e0.z;
    o[3] = (v[3]-mean)*rstd*g0.w + e0.w;
    o[4] = (v[4]-mean)*rstd*g1.x + e1.x;
    o[5] = (v[5]-mean)*rstd*g1.y + e1.y;
    o[6] = (v[6]-mean)*rstd*g1.z + e1.z;
    o[7] = (v[7]-mean)*rstd*g1.w + e1.w;
}

// Fused 2-layer MLP+LN embed (single-buffered — R2 version, proven fast).
// Block: 64 rows x 256 cols, 256 threads.
#define EMBED_SMEM ((64*256 + 16*256 + 64*16) * 4)

__global__ __launch_bounds__(256)
void embed_kernel(const float* __restrict__ xA, const float* __restrict__ xB,
                  const float* __restrict__ W1, const float* __restrict__ b1,
                  const float* __restrict__ g1, const float* __restrict__ be1,
                  const float* __restrict__ W2, const float* __restrict__ b2,
                  const float* __restrict__ g2, const float* __restrict__ be2)
{
    extern __shared__ float sm[];
    float* Hs = sm;              // 64*256
    float* Ws = sm + 64*256;     // 16*256
    float* As = Ws + 16*256;     // 64*16

    const float* X  = blockIdx.y ? xB   : xA;
    float* E        = blockIdx.y ? g_eB : g_eA;
    float* NRM      = blockIdx.y ? g_nB : g_nA;

    const int tid  = threadIdx.x;
    const int lane = tid & 31;
    const int warp = tid >> 5;
    const int row0 = blockIdx.x * 64;
    const int wr   = warp * 8;
    const int c0   = lane * 4;
    const int c1   = 128 + lane * 4;

    float acc[8][8];
    #pragma unroll
    for (int r = 0; r < 8; r++)
        #pragma unroll
        for (int c = 0; c < 8; c++) acc[r][c] = 0.f;

    // stage 1: h = LN(leaky(x@W1+b1))
    for (int kt = 0; kt < 16; kt++) {
        {
            int rr = tid >> 2, cq = (tid & 3) << 2;
            *(float4*)(As + rr*16 + cq) =
                *(const float4*)(X + (size_t)(row0 + rr)*DD + kt*16 + cq);
            const float4* Wv = (const float4*)(W1 + kt*16*DD);
            float4* Wd = (float4*)Ws;
            #pragma unroll
            for (int i = 0; i < 4; i++) Wd[tid + i*256] = Wv[tid + i*256];
        }
        __syncthreads();
        #pragma unroll
        for (int kk = 0; kk < 16; kk++) {
            float4 w0 = *(const float4*)(Ws + kk*256 + c0);
            float4 w1 = *(const float4*)(Ws + kk*256 + c1);
            #pragma unroll
            for (int r = 0; r < 8; r++) {
                float a = As[(wr + r)*16 + kk];
                acc[r][0] = fmaf(a, w0.x, acc[r][0]);
                acc[r][1] = fmaf(a, w0.y, acc[r][1]);
                acc[r][2] = fmaf(a, w0.z, acc[r][2]);
                acc[r][3] = fmaf(a, w0.w, acc[r][3]);
                acc[r][4] = fmaf(a, w1.x, acc[r][4]);
                acc[r][5] = fmaf(a, w1.y, acc[r][5]);
                acc[r][6] = fmaf(a, w1.z, acc[r][6]);
                acc[r][7] = fmaf(a, w1.w, acc[r][7]);
            }
        }
        __syncthreads();
    }
    {
        float4 bv0 = *(const float4*)(b1 + c0), bv1 = *(const float4*)(b1 + c1);
        float4 gv0 = *(const float4*)(g1 + c0), gv1 = *(const float4*)(g1 + c1);
        float4 ev0 = *(const float4*)(be1 + c0), ev1 = *(const float4*)(be1 + c1);
        #pragma unroll
        for (int r = 0; r < 8; r++) {
            float v[8], o[8];
            v[0]=acc[r][0]+bv0.x; v[1]=acc[r][1]+bv0.y; v[2]=acc[r][2]+bv0.z; v[3]=acc[r][3]+bv0.w;
            v[4]=acc[r][4]+bv1.x; v[5]=acc[r][5]+bv1.y; v[6]=acc[r][6]+bv1.z; v[7]=acc[r][7]+bv1.w;
            ln_row(v, gv0, gv1, ev0, ev1, o);
            *(float4*)(Hs + (wr + r)*256 + c0) = make_float4(o[0],o[1],o[2],o[3]);
            *(float4*)(Hs + (wr + r)*256 + c1) = make_float4(o[4],o[5],o[6],o[7]);
        }
    }
    __syncthreads();
    #pragma unroll
    for (int r = 0; r < 8; r++)
        #pragma unroll
        for (int c = 0; c < 8; c++) acc[r][c] = 0.f;

    // stage 2: e = LN(leaky(h@W2+b2))
    for (int kt = 0; kt < 16; kt++) {
        {
            const float4* Wv = (const float4*)(W2 + kt*16*DD);
            float4* Wd = (float4*)Ws;
            #pragma unroll
            for (int i = 0; i < 4; i++) Wd[tid + i*256] = Wv[tid + i*256];
        }
        __syncthreads();
        #pragma unroll
        for (int kk = 0; kk < 16; kk++) {
            float4 w0 = *(const float4*)(Ws + kk*256 + c0);
            float4 w1 = *(const float4*)(Ws + kk*256 + c1);
            #pragma unroll
            for (int r = 0; r < 8; r++) {
                float a = Hs[(wr + r)*256 + kt*16 + kk];
                acc[r][0] = fmaf(a, w0.x, acc[r][0]);
                acc[r][1] = fmaf(a, w0.y, acc[r][1]);
                acc[r][2] = fmaf(a, w0.z, acc[r][2]);
                acc[r][3] = fmaf(a, w0.w, acc[r][3]);
                acc[r][4] = fmaf(a, w1.x, acc[r][4]);
                acc[r][5] = fmaf(a, w1.y, acc[r][5]);
                acc[r][6] = fmaf(a, w1.z, acc[r][6]);
                acc[r][7] = fmaf(a, w1.w, acc[r][7]);
            }
        }
        __syncthreads();
    }
    {
        float4 bv0 = *(const float4*)(b2 + c0), bv1 = *(const float4*)(b2 + c1);
        float4 gv0 = *(const float4*)(g2 + c0), gv1 = *(const float4*)(g2 + c1);
        float4 ev0 = *(const float4*)(be2 + c0), ev1 = *(const float4*)(be2 + c1);
        #pragma unroll
        for (int r = 0; r < 8; r++) {
            float v[8], o[8];
            v[0]=acc[r][0]+bv0.x; v[1]=acc[r][1]+bv0.y; v[2]=acc[r][2]+bv0.z; v[3]=acc[r][3]+bv0.w;
            v[4]=acc[r][4]+bv1.x; v[5]=acc[r][5]+bv1.y; v[6]=acc[r][6]+bv1.z; v[7]=acc[r][7]+bv1.w;
            ln_row(v, gv0, gv1, ev0, ev1, o);
            float ns = o[0]*o[0]+o[1]*o[1]+o[2]*o[2]+o[3]*o[3]
                     + o[4]*o[4]+o[5]*o[5]+o[6]*o[6]+o[7]*o[7];
            #pragma unroll
            for (int off = 16; off; off >>= 1)
                ns += __shfl_xor_sync(0xffffffffu, ns, off);
            size_t grow = (size_t)(row0 + wr + r);
            *(float4*)(E + grow*DD + c0) = make_float4(o[0],o[1],o[2],o[3]);
            *(float4*)(E + grow*DD + c1) = make_float4(o[4],o[5],o[6],o[7]);
            if (lane == 0) NRM[grow] = ns;
        }
    }
}

// cdist + cost_class + in/out loss + K(bf16), double-buffered (proven R4 win).
__global__ __launch_bounds__(256, 2)
void cost_kernel(const float* __restrict__ pa, const float* __restrict__ pb)
{
    __shared__ __align__(16) float Ast[2][16][132];
    __shared__ __align__(16) float Bst[2][16][132];
    __shared__ float redi[8], redo[8];

    const int b  = blockIdx.z;
    const int ti = blockIdx.y;
    const int tj = blockIdx.x;
    const int tid = threadIdx.x;
    const int ty = tid >> 4;
    const int tx = tid & 15;

    const float* Ab = g_eA + (size_t)b*NN*DD + (size_t)ti*128*DD;
    const float* Bb = g_eB + (size_t)b*NN*DD + (size_t)tj*128*DD;

    float acc[8][8];
    #pragma unroll
    for (int r = 0; r < 8; r++)
        #pragma unroll
        for (int c = 0; c < 8; c++) acc[r][c] = 0.f;

    float4 avr[2], bvr[2];
    #pragma unroll
    for (int s = 0; s < 2; s++) {
        int idx = tid + s*256;
        int row = idx >> 2, cq = (idx & 3) << 2;
        avr[s] = *(const float4*)(Ab + (size_t)row*DD + cq);
        bvr[s] = *(const float4*)(Bb + (size_t)row*DD + cq);
    }
    #pragma unroll
    for (int s = 0; s < 2; s++) {
        int idx = tid + s*256;
        int row = idx >> 2, cq = (idx & 3) << 2;
        Ast[0][cq+0][row]=avr[s].x; Ast[0][cq+1][row]=avr[s].y;
        Ast[0][cq+2][row]=avr[s].z; Ast[0][cq+3][row]=avr[s].w;
        Bst[0][cq+0][row]=bvr[s].x; Bst[0][cq+1][row]=bvr[s].y;
        Bst[0][cq+2][row]=bvr[s].z; Bst[0][cq+3][row]=bvr[s].w;
    }
    __syncthreads();

    for (int kt = 0; kt < 16; kt++) {
        const int cur = kt & 1, nxt = cur ^ 1;
        if (kt < 15) {
            #pragma unroll
            for (int s = 0; s < 2; s++) {
                int idx = tid + s*256;
                int row = idx >> 2, cq = (idx & 3) << 2;
                avr[s] = *(const float4*)(Ab + (size_t)row*DD + (kt+1)*16 + cq);
                bvr[s] = *(const float4*)(Bb + (size_t)row*DD + (kt+1)*16 + cq);
            }
        }
        #pragma unroll
        for (int kk = 0; kk < 16; kk++) {
            float4 a0 = *(const float4*)(&Ast[cur][kk][ty*4]);
            float4 a1 = *(const float4*)(&Ast[cur][kk][64 + ty*4]);
            float4 b0 = *(const float4*)(&Bst[cur][kk][tx*4]);
            float4 b1 = *(const float4*)(&Bst[cur][kk][64 + tx*4]);
            float ar[8] = {a0.x,a0.y,a0.z,a0.w,a1.x,a1.y,a1.z,a1.w};
            float br[8] = {b0.x,b0.y,b0.z,b0.w,b1.x,b1.y,b1.z,b1.w};
            #pragma unroll
            for (int r = 0; r < 8; r++)
                #pragma unroll
                for (int c = 0; c < 8; c++)
                    acc[r][c] = fmaf(ar[r], br[c], acc[r][c]);
        }
        if (kt < 15) {
            #pragma unroll
            for (int s = 0; s < 2; s++) {
                int idx = tid + s*256;
                int row = idx >> 2, cq = (idx & 3) << 2;
                Ast[nxt][cq+0][row]=avr[s].x; Ast[nxt][cq+1][row]=avr[s].y;
                Ast[nxt][cq+2][row]=avr[s].z; Ast[nxt][cq+3][row]=avr[s].w;
                Bst[nxt][cq+0][row]=bvr[s].x; Bst[nxt][cq+1][row]=bvr[s].y;
                Bst[nxt][cq+2][row]=bvr[s].z; Bst[nxt][cq+3][row]=bvr[s].w;
            }
        }
        __syncthreads();
    }

    float ni[8], pav[8]; int cai[8];
    float njv[8], pbv[8]; int cbj[8];
    #pragma unroll
    for (int r = 0; r < 8; r++) {
        int il = ti*128 + ((r < 4) ? ty*4 + r : 64 + ty*4 + (r-4));
        int gi = b*NN + il;
        ni[r] = g_nA[gi]; pav[r] = pa[gi]; cai[r] = g_cA[gi];
    }
    #pragma unroll
    for (int c = 0; c < 8; c++) {
        int jl = tj*128 + ((c < 4) ? tx*4 + c : 64 + tx*4 + (c-4));
        int gj = b*NN + jl;
        njv[c] = g_nB[gj]; pbv[c] = pb[gj]; cbj[c] = g_cB[gj];
    }

    float sin = 0.f, sout = 0.f;
    #pragma unroll
    for (int r = 0; r < 8; r++) {
        int il = ti*128 + ((r < 4) ? ty*4 + r : 64 + ty*4 + (r-4));
        size_t rowb = ((size_t)(b*NN + il)) * NN;
        #pragma unroll
        for (int cg = 0; cg < 2; cg++) {
            float kv[4];
            #pragma unroll
            for (int c4 = 0; c4 < 4; c4++) {
                int c = cg*4 + c4;
                float sq   = ni[r] + njv[c] - 2.f*acc[r][c];
                float cost = sqrtf(fmaxf(sq, 0.f));
                float pm   = pav[r]*pbv[c];
                float cc   = cost + (BIGC - BIGC*pm);
                float w    = cc * pm;
                if (cai[r] == cbj[c]) sin += w; else sout += w;
                kv[c4] = __expf(-2.f*cc);
            }
            uint2 pk;
            pk.x = pack_bf2(kv[0], kv[1]);
            pk.y = pack_bf2(kv[2], kv[3]);
            *(uint2*)(g_K + rowb + tj*128 + cg*64 + tx*4) = pk;
        }
    }
    #pragma unroll
    for (int off = 16; off; off >>= 1) {
        sin  += __shfl_xor_sync(0xffffffffu, sin,  off);
        sout += __shfl_xor_sync(0xffffffffu, sout, off);
    }
    int lane = tid & 31, warp = tid >> 5;
    if (lane == 0) { redi[warp] = sin; redo[warp] = sout; }
    __syncthreads();
    if (tid == 0) {
        float a = 0.f, o2 = 0.f;
        #pragma unroll
        for (int w = 0; w < 8; w++) { a += redi[w]; o2 += redo[w]; }
        atomicAdd(&g_acc[0], (double)a);
        atomicAdd(&g_acc[1], (double)o2);
    }
}

// Sinkhorn, 1 CTA per batch, K (bf16) resident in L2.
__global__ __launch_bounds__(512)
void sinkhorn_kernel()
{
    __shared__ __align__(16) float su[NN];
    __shared__ __align__(16) float sv[NN];
    __shared__ __align__(16) float part[4][NN];

    const int b = blockIdx.x;
    const __nv_bfloat16* Kb = g_K + (size_t)b*NN*NN;
    const int tid  = threadIdx.x;
    const int lane = tid & 31;
    const int warp = tid >> 5;
    const int grp  = tid >> 7;
    const int jc   = (tid & 127) * 4;

    su[tid] = 1.f/512.f;
    __syncthreads();

    for (int it = 0; it < 10; it++) {
        // v = b / (K^T u)
        float a0 = 0.f, a1 = 0.f, a2 = 0.f, a3 = 0.f;
        const int i0 = grp * 128;
        const uint2* K2 = (const uint2*)Kb;
        #pragma unroll 4
        for (int i = 0; i < 128; i++) {
            uint2 kq = K2[(((size_t)(i0 + i))*NN + jc) >> 2];
            float k0,k1,k2,k3;
            unpack_bf2(kq.x, k0, k1);
            unpack_bf2(kq.y, k2, k3);
            float ui = su[i0 + i];
            a0 = fmaf(k0, ui, a0);
            a1 = fmaf(k1, ui, a1);
            a2 = fmaf(k2, ui, a2);
            a3 = fmaf(k3, ui, a3);
        }
        *(float4*)(&part[grp][jc]) = make_float4(a0,a1,a2,a3);
        __syncthreads();
        {
            float y = part[0][tid] + part[1][tid] + part[2][tid] + part[3][tid];
            sv[tid] = (1.f/512.f) / y;
        }
        __syncthreads();
        // u = a / (K v), warp per row; lane owns cols lane*16..+15
        for (int rr = 0; rr < 32; rr++) {
            int i = warp*32 + rr;
            const uint4* kr = (const uint4*)(Kb + (size_t)i*NN);
            uint4 q0 = kr[lane*2];
            uint4 q1 = kr[lane*2 + 1];
            float s = 0.f;
            float k0,k1;
            float4 vv;
            vv = *(const float4*)(sv + lane*16 + 0);
            unpack_bf2(q0.x, k0, k1); s = fmaf(k0, vv.x, s); s = fmaf(k1, vv.y, s);
            unpack_bf2(q0.y, k0, k1); s = fmaf(k0, vv.z, s); s = fmaf(k1, vv.w, s);
            vv = *(const float4*)(sv + lane*16 + 4);
            unpack_bf2(q0.z, k0, k1); s = fmaf(k0, vv.x, s); s = fmaf(k1, vv.y, s);
            unpack_bf2(q0.w, k0, k1); s = fmaf(k0, vv.z, s); s = fmaf(k1, vv.w, s);
            vv = *(const float4*)(sv + lane*16 + 8);
            unpack_bf2(q1.x, k0, k1); s = fmaf(k0, vv.x, s); s = fmaf(k1, vv.y, s);
            unpack_bf2(q1.y, k0, k1); s = fmaf(k0, vv.z, s); s = fmaf(k1, vv.w, s);
            vv = *(const float4*)(sv + lane*16 + 12);
            unpack_bf2(q1.z, k0, k1); s = fmaf(k0, vv.x, s); s = fmaf(k1, vv.y, s);
            unpack_bf2(q1.w, k0, k1); s = fmaf(k0, vv.z, s); s = fmaf(k1, vv.w, s);
            #pragma unroll
            for (int off = 16; off; off >>= 1)
                s += __shfl_xor_sync(0xffffffffu, s, off);
            if (lane == 0) su[i] = (1.f/512.f) / s;
        }
        __syncthreads();
    }
    g_u[b*NN + tid] = su[tid];
    g_v[b*NN + tid] = sv[tid];
}

__global__ void sup_kernel(const float* __restrict__ rel,
                           const float* __restrict__ pa)
{
    __shared__ float red[8];
    const size_t total8 = (size_t)BSZ*NN*NN/8;
    float lacc = 0.f;
    for (size_t idx = (size_t)blockIdx.x*blockDim.x + threadIdx.x; idx < total8;
         idx += (size_t)gridDim.x*blockDim.x) {
        size_t e = idx * 8;
        int b = (int)(e >> 18);
        int i = (int)((e >> 9) & 511);
        int j = (int)(e & 511);
        uint4 kq = ((const uint4*)g_K)[idx];
        float kf[8];
        unpack_bf2(kq.x, kf[0], kf[1]);
        unpack_bf2(kq.y, kf[2], kf[3]);
        unpack_bf2(kq.z, kf[4], kf[5]);
        unpack_bf2(kq.w, kf[6], kf[7]);
        float4 rv0 = ((const float4*)rel)[idx*2];
        float4 rv1 = ((const float4*)rel)[idx*2 + 1];
        float ui  = g_u[b*NN + i] * 512.f;
        float pai = pa[b*NN + i];
        float4 vv0 = *(const float4*)(g_v + b*NN + j);
        float4 vv1 = *(const float4*)(g_v + b*NN + j + 4);
        float d0 = ui*kf[0]*vv0.x - rv0.x;
        float d1 = ui*kf[1]*vv0.y - rv0.y;
        float d2 = ui*kf[2]*vv0.z - rv0.z;
        float d3 = ui*kf[3]*vv0.w - rv0.w;
        float d4 = ui*kf[4]*vv1.x - rv1.x;
        float d5 = ui*kf[5]*vv1.y - rv1.y;
        float d6 = ui*kf[6]*vv1.z - rv1.z;
        float d7 = ui*kf[7]*vv1.w - rv1.w;
        lacc += pai * (d0*d0 + d1*d1 + d2*d2 + d3*d3
                     + d4*d4 + d5*d5 + d6*d6 + d7*d7);
    }
    #pragma unroll
    for (int off = 16; off; off >>= 1)
        lacc += __shfl_xor_sync(0xffffffffu, lacc, off);
    int lane = threadIdx.x & 31, warp = threadIdx.x >> 5;
    if (lane == 0) red[warp] = lacc;
    __syncthreads();
    if (threadIdx.x == 0) {
        float s = 0.f;
        #pragma unroll
        for (int w = 0; w < 8; w++) s += red[w];
        atomicAdd(&g_acc[2], (double)s);
    }
}

__global__ void finalize_kernel(const float* __restrict__ pa, float* __restrict__ out)
{
    __shared__ float red[256];
    float s = 0.f;
    for (int i = threadIdx.x; i < BSZ*NN; i += 256) s += pa[i];
    red[threadIdx.x] = s;
    __syncthreads();
    for (int off = 128; off; off >>= 1) {
        if (threadIdx.x < off) red[threadIdx.x] += red[threadIdx.x + off];
        __syncthreads();
    }
    if (threadIdx.x == 0) {
        double M = (double)BSZ * (double)NN * (double)NN;
        out[0] = (float)(g_acc[0]/M - g_acc[1]/M + 10.0*(g_acc[2]/(double)red[0]));
    }
}

extern "C" void kernel_launch(void* const* d_in, const int* in_sizes, int n_in,
                              void* d_out, int out_size)
{
    const float* la  = (const float*)d_in[0];
    const float* lb  = (const float*)d_in[1];
    const float* xA  = (const float*)d_in[2];
    const float* xB  = (const float*)d_in[3];
    const float* rel = (const float*)d_in[4];
    const float* pa  = (const float*)d_in[5];
    const float* pb  = (const float*)d_in[6];
    const float* W1  = (const float*)d_in[7];
    const float* b1  = (const float*)d_in[8];
    const float* g1  = (const float*)d_in[9];
    const float* be1 = (const float*)d_in[10];
    const float* W2  = (const float*)d_in[11];
    const float* b2  = (const float*)d_in[12];
    const float* g2  = (const float*)d_in[13];
    const float* be2 = (const float*)d_in[14];
    float* out = (float*)d_out;

    cudaFuncSetAttribute(embed_kernel,
                         cudaFuncAttributeMaxDynamicSharedMemorySize, EMBED_SMEM);

    zero_acc_kernel<<<1, 32>>>();
    class_argmax_kernel<<<(BSZ*NN + 255)/256, 256>>>(la, lb);
    embed_kernel<<<dim3(BSZ*NN/64, 2), 256, EMBED_SMEM>>>(
        xA, xB, W1, b1, g1, be1, W2, b2, g2, be2);
    cost_kernel<<<dim3(4, 4, BSZ), 256>>>(pa, pb);
    sinkhorn_kernel<<<BSZ, 512>>>();
    sup_kernel<<<2048, 256>>>(rel, pa);
    finalize_kernel<<<1, 256>>>(pa, out);
}

// round 6
// speedup vs baseline: 1.2896x; 1.1084x over previous
#include <cuda_runtime.h>
#include <cuda_bf16.h>
#include <stdint.h>
#include <math.h>

#define BSZ 64
#define NN 512
#define DD 256
#define BIGC 1.0e9f

__device__ float g_eA[BSZ*NN*DD];
__device__ float g_eB[BSZ*NN*DD];
__device__ float g_nA[BSZ*NN];
__device__ float g_nB[BSZ*NN];
__device__ __nv_bfloat16 g_K[(size_t)BSZ*NN*NN];
__device__ int   g_cA[BSZ*NN];
__device__ int   g_cB[BSZ*NN];
__device__ double g_acc[3];

// ---- bf16 helpers ----
__device__ __forceinline__ uint32_t pack_bf2(float a, float b) {
    __nv_bfloat162 h = __floats2bfloat162_rn(a, b);
    return *reinterpret_cast<uint32_t*>(&h);
}
__device__ __forceinline__ void unpack_bf2(uint32_t u, float& a, float& b) {
    a = __uint_as_float(u << 16);
    b = __uint_as_float(u & 0xffff0000u);
}

__global__ void zero_acc_kernel() {
    if (threadIdx.x < 3) g_acc[threadIdx.x] = 0.0;
}

__global__ void class_argmax_kernel(const float* __restrict__ la,
                                    const float* __restrict__ lb) {
    int t = blockIdx.x * blockDim.x + threadIdx.x;
    if (t >= BSZ*NN) return;
    float4 a = ((const float4*)la)[t];
    int ba = 0; float bv = a.x;
    if (a.y > bv) { bv = a.y; ba = 1; }
    if (a.z > bv) { bv = a.z; ba = 2; }
    if (a.w > bv) { bv = a.w; ba = 3; }
    g_cA[t] = ba;
    float4 b = ((const float4*)lb)[t];
    int bb = 0; bv = b.x;
    if (b.y > bv) { bv = b.y; bb = 1; }
    if (b.z > bv) { bv = b.z; bb = 2; }
    if (b.w > bv) { bv = b.w; bb = 3; }
    g_cB[t] = bb;
}

__device__ __forceinline__ void ln_row(float v[8],
    const float4& g0, const float4& g1, const float4& e0, const float4& e1,
    float* o)
{
    float s = 0.f, sq = 0.f;
    #pragma unroll
    for (int j = 0; j < 8; j++) {
        v[j] = v[j] > 0.f ? v[j] : 0.01f * v[j];
        s += v[j]; sq += v[j]*v[j];
    }
    #pragma unroll
    for (int off = 16; off; off >>= 1) {
        s  += __shfl_xor_sync(0xffffffffu, s, off);
        sq += __shfl_xor_sync(0xffffffffu, sq, off);
    }
    float mean = s * (1.f/256.f);
    float var  = sq * (1.f/256.f) - mean*mean;
    float rstd = rsqrtf(var + 1e-5f);
    o[0] = (v[0]-mean)*rstd*g0.x + e0.x;
    o[1] = (v[1]-mean)*rstd*g0.y + e0.y;
    o[2] = (v[2]-mean)*rstd*g0.z + e0.z;
    o[3] = (v[3]-mean)*rstd*g0.w + e0.w;
    o[4] = (v[4]-mean)*rstd*g1.x + e1.x;
    o[5] = (v[5]-mean)*rstd*g1.y + e1.y;
    o[6] = (v[6]-mean)*rstd*g1.z + e1.z;
    o[7] = (v[7]-mean)*rstd*g1.w + e1.w;
}

// Fused 2-layer MLP+LN embed (single-buffered — proven fast, unchanged).
#define EMBED_SMEM ((64*256 + 16*256 + 64*16) * 4)

__global__ __launch_bounds__(256)
void embed_kernel(const float* __restrict__ xA, const float* __restrict__ xB,
                  const float* __restrict__ W1, const float* __restrict__ b1,
                  const float* __restrict__ g1, const float* __restrict__ be1,
                  const float* __restrict__ W2, const float* __restrict__ b2,
                  const float* __restrict__ g2, const float* __restrict__ be2)
{
    extern __shared__ float sm[];
    float* Hs = sm;              // 64*256
    float* Ws = sm + 64*256;     // 16*256
    float* As = Ws + 16*256;     // 64*16

    const float* X  = blockIdx.y ? xB   : xA;
    float* E        = blockIdx.y ? g_eB : g_eA;
    float* NRM      = blockIdx.y ? g_nB : g_nA;

    const int tid  = threadIdx.x;
    const int lane = tid & 31;
    const int warp = tid >> 5;
    const int row0 = blockIdx.x * 64;
    const int wr   = warp * 8;
    const int c0   = lane * 4;
    const int c1   = 128 + lane * 4;

    float acc[8][8];
    #pragma unroll
    for (int r = 0; r < 8; r++)
        #pragma unroll
        for (int c = 0; c < 8; c++) acc[r][c] = 0.f;

    // stage 1: h = LN(leaky(x@W1+b1))
    for (int kt = 0; kt < 16; kt++) {
        {
            int rr = tid >> 2, cq = (tid & 3) << 2;
            *(float4*)(As + rr*16 + cq) =
                *(const float4*)(X + (size_t)(row0 + rr)*DD + kt*16 + cq);
            const float4* Wv = (const float4*)(W1 + kt*16*DD);
            float4* Wd = (float4*)Ws;
            #pragma unroll
            for (int i = 0; i < 4; i++) Wd[tid + i*256] = Wv[tid + i*256];
        }
        __syncthreads();
        #pragma unroll
        for (int kk = 0; kk < 16; kk++) {
            float4 w0 = *(const float4*)(Ws + kk*256 + c0);
            float4 w1 = *(const float4*)(Ws + kk*256 + c1);
            #pragma unroll
            for (int r = 0; r < 8; r++) {
                float a = As[(wr + r)*16 + kk];
                acc[r][0] = fmaf(a, w0.x, acc[r][0]);
                acc[r][1] = fmaf(a, w0.y, acc[r][1]);
                acc[r][2] = fmaf(a, w0.z, acc[r][2]);
                acc[r][3] = fmaf(a, w0.w, acc[r][3]);
                acc[r][4] = fmaf(a, w1.x, acc[r][4]);
                acc[r][5] = fmaf(a, w1.y, acc[r][5]);
                acc[r][6] = fmaf(a, w1.z, acc[r][6]);
                acc[r][7] = fmaf(a, w1.w, acc[r][7]);
            }
        }
        __syncthreads();
    }
    {
        float4 bv0 = *(const float4*)(b1 + c0), bv1 = *(const float4*)(b1 + c1);
        float4 gv0 = *(const float4*)(g1 + c0), gv1 = *(const float4*)(g1 + c1);
        float4 ev0 = *(const float4*)(be1 + c0), ev1 = *(const float4*)(be1 + c1);
        #pragma unroll
        for (int r = 0; r < 8; r++) {
            float v[8], o[8];
            v[0]=acc[r][0]+bv0.x; v[1]=acc[r][1]+bv0.y; v[2]=acc[r][2]+bv0.z; v[3]=acc[r][3]+bv0.w;
            v[4]=acc[r][4]+bv1.x; v[5]=acc[r][5]+bv1.y; v[6]=acc[r][6]+bv1.z; v[7]=acc[r][7]+bv1.w;
            ln_row(v, gv0, gv1, ev0, ev1, o);
            *(float4*)(Hs + (wr + r)*256 + c0) = make_float4(o[0],o[1],o[2],o[3]);
            *(float4*)(Hs + (wr + r)*256 + c1) = make_float4(o[4],o[5],o[6],o[7]);
        }
    }
    __syncthreads();
    #pragma unroll
    for (int r = 0; r < 8; r++)
        #pragma unroll
        for (int c = 0; c < 8; c++) acc[r][c] = 0.f;

    // stage 2: e = LN(leaky(h@W2+b2))
    for (int kt = 0; kt < 16; kt++) {
        {
            const float4* Wv = (const float4*)(W2 + kt*16*DD);
            float4* Wd = (float4*)Ws;
            #pragma unroll
            for (int i = 0; i < 4; i++) Wd[tid + i*256] = Wv[tid + i*256];
        }
        __syncthreads();
        #pragma unroll
        for (int kk = 0; kk < 16; kk++) {
            float4 w0 = *(const float4*)(Ws + kk*256 + c0);
            float4 w1 = *(const float4*)(Ws + kk*256 + c1);
            #pragma unroll
            for (int r = 0; r < 8; r++) {
                float a = Hs[(wr + r)*256 + kt*16 + kk];
                acc[r][0] = fmaf(a, w0.x, acc[r][0]);
                acc[r][1] = fmaf(a, w0.y, acc[r][1]);
                acc[r][2] = fmaf(a, w0.z, acc[r][2]);
                acc[r][3] = fmaf(a, w0.w, acc[r][3]);
                acc[r][4] = fmaf(a, w1.x, acc[r][4]);
                acc[r][5] = fmaf(a, w1.y, acc[r][5]);
                acc[r][6] = fmaf(a, w1.z, acc[r][6]);
                acc[r][7] = fmaf(a, w1.w, acc[r][7]);
            }
        }
        __syncthreads();
    }
    {
        float4 bv0 = *(const float4*)(b2 + c0), bv1 = *(const float4*)(b2 + c1);
        float4 gv0 = *(const float4*)(g2 + c0), gv1 = *(const float4*)(g2 + c1);
        float4 ev0 = *(const float4*)(be2 + c0), ev1 = *(const float4*)(be2 + c1);
        #pragma unroll
        for (int r = 0; r < 8; r++) {
            float v[8], o[8];
            v[0]=acc[r][0]+bv0.x; v[1]=acc[r][1]+bv0.y; v[2]=acc[r][2]+bv0.z; v[3]=acc[r][3]+bv0.w;
            v[4]=acc[r][4]+bv1.x; v[5]=acc[r][5]+bv1.y; v[6]=acc[r][6]+bv1.z; v[7]=acc[r][7]+bv1.w;
            ln_row(v, gv0, gv1, ev0, ev1, o);
            float ns = o[0]*o[0]+o[1]*o[1]+o[2]*o[2]+o[3]*o[3]
                     + o[4]*o[4]+o[5]*o[5]+o[6]*o[6]+o[7]*o[7];
            #pragma unroll
            for (int off = 16; off; off >>= 1)
                ns += __shfl_xor_sync(0xffffffffu, ns, off);
            size_t grow = (size_t)(row0 + wr + r);
            *(float4*)(E + grow*DD + c0) = make_float4(o[0],o[1],o[2],o[3]);
            *(float4*)(E + grow*DD + c1) = make_float4(o[4],o[5],o[6],o[7]);
            if (lane == 0) NRM[grow] = ns;
        }
    }
}

// cdist + cost_class + in/out loss + K(bf16), double-buffered (unchanged).
__global__ __launch_bounds__(256, 2)
void cost_kernel(const float* __restrict__ pa, const float* __restrict__ pb)
{
    __shared__ __align__(16) float Ast[2][16][132];
    __shared__ __align__(16) float Bst[2][16][132];
    __shared__ float redi[8], redo[8];

    const int b  = blockIdx.z;
    const int ti = blockIdx.y;
    const int tj = blockIdx.x;
    const int tid = threadIdx.x;
    const int ty = tid >> 4;
    const int tx = tid & 15;

    const float* Ab = g_eA + (size_t)b*NN*DD + (size_t)ti*128*DD;
    const float* Bb = g_eB + (size_t)b*NN*DD + (size_t)tj*128*DD;

    float acc[8][8];
    #pragma unroll
    for (int r = 0; r < 8; r++)
        #pragma unroll
        for (int c = 0; c < 8; c++) acc[r][c] = 0.f;

    float4 avr[2], bvr[2];
    #pragma unroll
    for (int s = 0; s < 2; s++) {
        int idx = tid + s*256;
        int row = idx >> 2, cq = (idx & 3) << 2;
        avr[s] = *(const float4*)(Ab + (size_t)row*DD + cq);
        bvr[s] = *(const float4*)(Bb + (size_t)row*DD + cq);
    }
    #pragma unroll
    for (int s = 0; s < 2; s++) {
        int idx = tid + s*256;
        int row = idx >> 2, cq = (idx & 3) << 2;
        Ast[0][cq+0][row]=avr[s].x; Ast[0][cq+1][row]=avr[s].y;
        Ast[0][cq+2][row]=avr[s].z; Ast[0][cq+3][row]=avr[s].w;
        Bst[0][cq+0][row]=bvr[s].x; Bst[0][cq+1][row]=bvr[s].y;
        Bst[0][cq+2][row]=bvr[s].z; Bst[0][cq+3][row]=bvr[s].w;
    }
    __syncthreads();

    for (int kt = 0; kt < 16; kt++) {
        const int cur = kt & 1, nxt = cur ^ 1;
        if (kt < 15) {
            #pragma unroll
            for (int s = 0; s < 2; s++) {
                int idx = tid + s*256;
                int row = idx >> 2, cq = (idx & 3) << 2;
                avr[s] = *(const float4*)(Ab + (size_t)row*DD + (kt+1)*16 + cq);
                bvr[s] = *(const float4*)(Bb + (size_t)row*DD + (kt+1)*16 + cq);
            }
        }
        #pragma unroll
        for (int kk = 0; kk < 16; kk++) {
            float4 a0 = *(const float4*)(&Ast[cur][kk][ty*4]);
            float4 a1 = *(const float4*)(&Ast[cur][kk][64 + ty*4]);
            float4 b0 = *(const float4*)(&Bst[cur][kk][tx*4]);
            float4 b1 = *(const float4*)(&Bst[cur][kk][64 + tx*4]);
            float ar[8] = {a0.x,a0.y,a0.z,a0.w,a1.x,a1.y,a1.z,a1.w};
            float br[8] = {b0.x,b0.y,b0.z,b0.w,b1.x,b1.y,b1.z,b1.w};
            #pragma unroll
            for (int r = 0; r < 8; r++)
                #pragma unroll
                for (int c = 0; c < 8; c++)
                    acc[r][c] = fmaf(ar[r], br[c], acc[r][c]);
        }
        if (kt < 15) {
            #pragma unroll
            for (int s = 0; s < 2; s++) {
                int idx = tid + s*256;
                int row = idx >> 2, cq = (idx & 3) << 2;
                Ast[nxt][cq+0][row]=avr[s].x; Ast[nxt][cq+1][row]=avr[s].y;
                Ast[nxt][cq+2][row]=avr[s].z; Ast[nxt][cq+3][row]=avr[s].w;
                Bst[nxt][cq+0][row]=bvr[s].x; Bst[nxt][cq+1][row]=bvr[s].y;
                Bst[nxt][cq+2][row]=bvr[s].z; Bst[nxt][cq+3][row]=bvr[s].w;
            }
        }
        __syncthreads();
    }

    float ni[8], pav[8]; int cai[8];
    float njv[8], pbv[8]; int cbj[8];
    #pragma unroll
    for (int r = 0; r < 8; r++) {
        int il = ti*128 + ((r < 4) ? ty*4 + r : 64 + ty*4 + (r-4));
        int gi = b*NN + il;
        ni[r] = g_nA[gi]; pav[r] = pa[gi]; cai[r] = g_cA[gi];
    }
    #pragma unroll
    for (int c = 0; c < 8; c++) {
        int jl = tj*128 + ((c < 4) ? tx*4 + c : 64 + tx*4 + (c-4));
        int gj = b*NN + jl;
        njv[c] = g_nB[gj]; pbv[c] = pb[gj]; cbj[c] = g_cB[gj];
    }

    float sin = 0.f, sout = 0.f;
    #pragma unroll
    for (int r = 0; r < 8; r++) {
        int il = ti*128 + ((r < 4) ? ty*4 + r : 64 + ty*4 + (r-4));
        size_t rowb = ((size_t)(b*NN + il)) * NN;
        #pragma unroll
        for (int cg = 0; cg < 2; cg++) {
            float kv[4];
            #pragma unroll
            for (int c4 = 0; c4 < 4; c4++) {
                int c = cg*4 + c4;
                float sq   = ni[r] + njv[c] - 2.f*acc[r][c];
                float cost = sqrtf(fmaxf(sq, 0.f));
                float pm   = pav[r]*pbv[c];
                float cc   = cost + (BIGC - BIGC*pm);
                float w    = cc * pm;
                if (cai[r] == cbj[c]) sin += w; else sout += w;
                kv[c4] = __expf(-2.f*cc);
            }
            uint2 pk;
            pk.x = pack_bf2(kv[0], kv[1]);
            pk.y = pack_bf2(kv[2], kv[3]);
            *(uint2*)(g_K + rowb + tj*128 + cg*64 + tx*4) = pk;
        }
    }
    #pragma unroll
    for (int off = 16; off; off >>= 1) {
        sin  += __shfl_xor_sync(0xffffffffu, sin,  off);
        sout += __shfl_xor_sync(0xffffffffu, sout, off);
    }
    int lane = tid & 31, warp = tid >> 5;
    if (lane == 0) { redi[warp] = sin; redo[warp] = sout; }
    __syncthreads();
    if (tid == 0) {
        float a = 0.f, o2 = 0.f;
        #pragma unroll
        for (int w = 0; w < 8; w++) { a += redi[w]; o2 += redo[w]; }
        atomicAdd(&g_acc[0], (double)a);
        atomicAdd(&g_acc[1], (double)o2);
    }
}

// Sinkhorn + fused sup loss. 1 CTA (1024 threads) per batch, K (bf16) in L2.
__global__ __launch_bounds__(1024)
void sinkhorn_kernel(const float* __restrict__ rel, const float* __restrict__ pa)
{
    __shared__ __align__(16) float su[NN];
    __shared__ __align__(16) float sv[NN];
    __shared__ __align__(16) float part[8][NN];
    __shared__ float sred[32];

    const int b = blockIdx.x;
    const __nv_bfloat16* Kb = g_K + (size_t)b*NN*NN;
    const int tid  = threadIdx.x;
    const int lane = tid & 31;
    const int warp = tid >> 5;
    const int grp  = tid >> 7;          // 0..7: i-range split (64 rows each)
    const int jc   = (tid & 127) * 4;   // owned 4 columns

    if (tid < NN) su[tid] = 1.f/512.f;
    __syncthreads();

    for (int it = 0; it < 10; it++) {
        // v = b / (K^T u): group g accumulates rows [g*64, g*64+64)
        float a0 = 0.f, a1 = 0.f, a2 = 0.f, a3 = 0.f;
        const int i0 = grp * 64;
        const uint2* K2 = (const uint2*)Kb;
        #pragma unroll 8
        for (int i = 0; i < 64; i++) {
            uint2 kq = K2[(((size_t)(i0 + i))*NN + jc) >> 2];
            float k0,k1,k2,k3;
            unpack_bf2(kq.x, k0, k1);
            unpack_bf2(kq.y, k2, k3);
            float ui = su[i0 + i];
            a0 = fmaf(k0, ui, a0);
            a1 = fmaf(k1, ui, a1);
            a2 = fmaf(k2, ui, a2);
            a3 = fmaf(k3, ui, a3);
        }
        *(float4*)(&part[grp][jc]) = make_float4(a0,a1,a2,a3);
        __syncthreads();
        if (tid < NN) {
            float y = part[0][tid] + part[1][tid] + part[2][tid] + part[3][tid]
                    + part[4][tid] + part[5][tid] + part[6][tid] + part[7][tid];
            sv[tid] = (1.f/512.f) / y;
        }
        __syncthreads();
        // u = a / (K v): warp per row, 16 rows per warp
        for (int rr = 0; rr < 16; rr++) {
            int i = warp*16 + rr;
            const uint4* kr = (const uint4*)(Kb + (size_t)i*NN);
            uint4 q0 = kr[lane*2];
            uint4 q1 = kr[lane*2 + 1];
            float s = 0.f;
            float k0,k1;
            float4 vv;
            vv = *(const float4*)(sv + lane*16 + 0);
            unpack_bf2(q0.x, k0, k1); s = fmaf(k0, vv.x, s); s = fmaf(k1, vv.y, s);
            unpack_bf2(q0.y, k0, k1); s = fmaf(k0, vv.z, s); s = fmaf(k1, vv.w, s);
            vv = *(const float4*)(sv + lane*16 + 4);
            unpack_bf2(q0.z, k0, k1); s = fmaf(k0, vv.x, s); s = fmaf(k1, vv.y, s);
            unpack_bf2(q0.w, k0, k1); s = fmaf(k0, vv.z, s); s = fmaf(k1, vv.w, s);
            vv = *(const float4*)(sv + lane*16 + 8);
            unpack_bf2(q1.x, k0, k1); s = fmaf(k0, vv.x, s); s = fmaf(k1, vv.y, s);
            unpack_bf2(q1.y, k0, k1); s = fmaf(k0, vv.z, s); s = fmaf(k1, vv.w, s);
            vv = *(const float4*)(sv + lane*16 + 12);
            unpack_bf2(q1.z, k0, k1); s = fmaf(k0, vv.x, s); s = fmaf(k1, vv.y, s);
            unpack_bf2(q1.w, k0, k1); s = fmaf(k0, vv.z, s); s = fmaf(k1, vv.w, s);
            #pragma unroll
            for (int off = 16; off; off >>= 1)
                s += __shfl_xor_sync(0xffffffffu, s, off);
            if (lane == 0) su[i] = (1.f/512.f) / s;
        }
        __syncthreads();
    }

    // ---- fused sup loss: sum over (i,j) of pa[i]*(u_i*K_ij*v_j*512 - rel_ij)^2
    const float* relb = rel + (size_t)b*NN*NN;
    float lacc = 0.f;
    // 512*512/8 = 32768 uint4-groups; 1024 threads -> 32 groups each
    for (int t = 0; t < 32; t++) {
        int idx = tid + t*1024;
        int e = idx * 8;
        int i = e >> 9;
        int j = e & 511;
        uint4 kq = ((const uint4*)Kb)[idx];
        float kf[8];
        unpack_bf2(kq.x, kf[0], kf[1]);
        unpack_bf2(kq.y, kf[2], kf[3]);
        unpack_bf2(kq.z, kf[4], kf[5]);
        unpack_bf2(kq.w, kf[6], kf[7]);
        float4 rv0 = *(const float4*)(relb + e);
        float4 rv1 = *(const float4*)(relb + e + 4);
        float ui  = su[i] * 512.f;
        float pai = pa[b*NN + i];
        float4 vv0 = *(const float4*)(sv + j);
        float4 vv1 = *(const float4*)(sv + j + 4);
        float d0 = ui*kf[0]*vv0.x - rv0.x;
        float d1 = ui*kf[1]*vv0.y - rv0.y;
        float d2 = ui*kf[2]*vv0.z - rv0.z;
        float d3 = ui*kf[3]*vv0.w - rv0.w;
        float d4 = ui*kf[4]*vv1.x - rv1.x;
        float d5 = ui*kf[5]*vv1.y - rv1.y;
        float d6 = ui*kf[6]*vv1.z - rv1.z;
        float d7 = ui*kf[7]*vv1.w - rv1.w;
        lacc += pai * (d0*d0 + d1*d1 + d2*d2 + d3*d3
                     + d4*d4 + d5*d5 + d6*d6 + d7*d7);
    }
    #pragma unroll
    for (int off = 16; off; off >>= 1)
        lacc += __shfl_xor_sync(0xffffffffu, lacc, off);
    if (lane == 0) sred[warp] = lacc;
    __syncthreads();
    if (tid == 0) {
        float s = 0.f;
        #pragma unroll
        for (int w = 0; w < 32; w++) s += sred[w];
        atomicAdd(&g_acc[2], (double)s);
    }
}

__global__ void finalize_kernel(const float* __restrict__ pa, float* __restrict__ out)
{
    __shared__ float red[256];
    float s = 0.f;
    for (int i = threadIdx.x; i < BSZ*NN; i += 256) s += pa[i];
    red[threadIdx.x] = s;
    __syncthreads();
    for (int off = 128; off; off >>= 1) {
        if (threadIdx.x < off) red[threadIdx.x] += red[threadIdx.x + off];
        __syncthreads();
    }
    if (threadIdx.x == 0) {
        double M = (double)BSZ * (double)NN * (double)NN;
        out[0] = (float)(g_acc[0]/M - g_acc[1]/M + 10.0*(g_acc[2]/(double)red[0]));
    }
}

extern "C" void kernel_launch(void* const* d_in, const int* in_sizes, int n_in,
                              void* d_out, int out_size)
{
    const float* la  = (const float*)d_in[0];
    const float* lb  = (const float*)d_in[1];
    const float* xA  = (const float*)d_in[2];
    const float* xB  = (const float*)d_in[3];
    const float* rel = (const float*)d_in[4];
    const float* pa  = (const float*)d_in[5];
    const float* pb  = (const float*)d_in[6];
    const float* W1  = (const float*)d_in[7];
    const float* b1  = (const float*)d_in[8];
    const float* g1  = (const float*)d_in[9];
    const float* be1 = (const float*)d_in[10];
    const float* W2  = (const float*)d_in[11];
    const float* b2  = (const float*)d_in[12];
    const float* g2  = (const float*)d_in[13];
    const float* be2 = (const float*)d_in[14];
    float* out = (float*)d_out;

    cudaFuncSetAttribute(embed_kernel,
                         cudaFuncAttributeMaxDynamicSharedMemorySize, EMBED_SMEM);

    zero_acc_kernel<<<1, 32>>>();
    class_argmax_kernel<<<(BSZ*NN + 255)/256, 256>>>(la, lb);
    embed_kernel<<<dim3(BSZ*NN/64, 2), 256, EMBED_SMEM>>>(
        xA, xB, W1, b1, g1, be1, W2, b2, g2, be2);
    cost_kernel<<<dim3(4, 4, BSZ), 256>>>(pa, pb);
    sinkhorn_kernel<<<BSZ, 1024>>>(rel, pa);
    finalize_kernel<<<1, 256>>>(pa, out);
}

// round 7
// speedup vs baseline: 1.3749x; 1.0662x over previous
#include <cuda_runtime.h>
#include <cuda_bf16.h>
#include <stdint.h>
#include <math.h>

#define BSZ 64
#define NN 512
#define DD 256
#define BIGC 1.0e9f

__device__ float g_eA[BSZ*NN*DD];
__device__ float g_eB[BSZ*NN*DD];
__device__ float g_nA[BSZ*NN];
__device__ float g_nB[BSZ*NN];
__device__ __nv_bfloat16 g_K[(size_t)BSZ*NN*NN];
__device__ int   g_cA[BSZ*NN];
__device__ int   g_cB[BSZ*NN];
__device__ double g_acc[3];

// ---- helpers ----
__device__ __forceinline__ uint32_t pack_bf2(float a, float b) {
    __nv_bfloat162 h = __floats2bfloat162_rn(a, b);
    return *reinterpret_cast<uint32_t*>(&h);
}
__device__ __forceinline__ void unpack_bf2(uint32_t u, float& a, float& b) {
    a = __uint_as_float(u << 16);
    b = __uint_as_float(u & 0xffff0000u);
}
__device__ __forceinline__ void cp_async16(void* smem_dst, const void* gmem_src) {
    uint32_t s = (uint32_t)__cvta_generic_to_shared(smem_dst);
    asm volatile("cp.async.cg.shared.global [%0], [%1], 16;" :: "r"(s), "l"(gmem_src));
}
__device__ __forceinline__ void cp_commit() {
    asm volatile("cp.async.commit_group;");
}
__device__ __forceinline__ void cp_wait0() {
    asm volatile("cp.async.wait_group 0;");
}

__global__ void zero_acc_kernel() {
    if (threadIdx.x < 3) g_acc[threadIdx.x] = 0.0;
}

__global__ void class_argmax_kernel(const float* __restrict__ la,
                                    const float* __restrict__ lb) {
    int t = blockIdx.x * blockDim.x + threadIdx.x;
    if (t >= BSZ*NN) return;
    float4 a = ((const float4*)la)[t];
    int ba = 0; float bv = a.x;
    if (a.y > bv) { bv = a.y; ba = 1; }
    if (a.z > bv) { bv = a.z; ba = 2; }
    if (a.w > bv) { bv = a.w; ba = 3; }
    g_cA[t] = ba;
    float4 b = ((const float4*)lb)[t];
    int bb = 0; bv = b.x;
    if (b.y > bv) { bv = b.y; bb = 1; }
    if (b.z > bv) { bv = b.z; bb = 2; }
    if (b.w > bv) { bv = b.w; bb = 3; }
    g_cB[t] = bb;
}

__device__ __forceinline__ void ln_row(float v[8],
    const float4& g0, const float4& g1, const float4& e0, const float4& e1,
    float* o)
{
    float s = 0.f, sq = 0.f;
    #pragma unroll
    for (int j = 0; j < 8; j++) {
        v[j] = v[j] > 0.f ? v[j] : 0.01f * v[j];
        s += v[j]; sq += v[j]*v[j];
    }
    #pragma unroll
    for (int off = 16; off; off >>= 1) {
        s  += __shfl_xor_sync(0xffffffffu, s, off);
        sq += __shfl_xor_sync(0xffffffffu, sq, off);
    }
    float mean = s * (1.f/256.f);
    float var  = sq * (1.f/256.f) - mean*mean;
    float rstd = rsqrtf(var + 1e-5f);
    o[0] = (v[0]-mean)*rstd*g0.x + e0.x;
    o[1] = (v[1]-mean)*rstd*g0.y + e0.y;
    o[2] = (v[2]-mean)*rstd*g0.z + e0.z;
    o[3] = (v[3]-mean)*rstd*g0.w + e0.w;
    o[4] = (v[4]-mean)*rstd*g1.x + e1.x;
    o[5] = (v[5]-mean)*rstd*g1.y + e1.y;
    o[6] = (v[6]-mean)*rstd*g1.z + e1.z;
    o[7] = (v[7]-mean)*rstd*g1.w + e1.w;
}

// Fused 2-layer MLP+LN embed, cp.async double-buffered tiles.
// Block: 64 rows x 256 cols, 256 threads.
#define EMBED_SMEM ((64*256 + 2*16*256 + 2*64*16) * 4)

__global__ __launch_bounds__(256)
void embed_kernel(const float* __restrict__ xA, const float* __restrict__ xB,
                  const float* __restrict__ W1, const float* __restrict__ b1,
                  const float* __restrict__ g1, const float* __restrict__ be1,
                  const float* __restrict__ W2, const float* __restrict__ b2,
                  const float* __restrict__ g2, const float* __restrict__ be2)
{
    extern __shared__ float sm[];
    float* Hs = sm;                  // 64*256
    float* Ws = sm + 64*256;         // 2 * 16*256
    float* As = Ws + 2*16*256;       // 2 * 64*16

    const float* X  = blockIdx.y ? xB   : xA;
    float* E        = blockIdx.y ? g_eB : g_eA;
    float* NRM      = blockIdx.y ? g_nB : g_nA;

    const int tid  = threadIdx.x;
    const int lane = tid & 31;
    const int warp = tid >> 5;
    const int row0 = blockIdx.x * 64;
    const int wr   = warp * 8;
    const int c0   = lane * 4;
    const int c1   = 128 + lane * 4;
    const int rr   = tid >> 2;
    const int cq   = (tid & 3) << 2;

    float acc[8][8];
    #pragma unroll
    for (int r = 0; r < 8; r++)
        #pragma unroll
        for (int c = 0; c < 8; c++) acc[r][c] = 0.f;

    // ---------------- stage 1: h = LN(leaky(x@W1+b1)) ----------------
    // prologue: async-load tile 0 into buffer 0
    #pragma unroll
    for (int i = 0; i < 4; i++)
        cp_async16(Ws + (tid + i*256)*4, W1 + (size_t)(tid + i*256)*4);
    cp_async16(As + rr*16 + cq, X + (size_t)(row0 + rr)*DD + cq);
    cp_commit();
    cp_wait0();
    __syncthreads();

    for (int kt = 0; kt < 16; kt++) {
        const int cur = kt & 1, nxt = cur ^ 1;
        if (kt < 15) {
            const float* Wsrc = W1 + (size_t)(kt+1)*16*DD;
            float* Wdst = Ws + nxt*16*256;
            #pragma unroll
            for (int i = 0; i < 4; i++)
                cp_async16(Wdst + (tid + i*256)*4, Wsrc + (size_t)(tid + i*256)*4);
            cp_async16(As + nxt*64*16 + rr*16 + cq,
                       X + (size_t)(row0 + rr)*DD + (kt+1)*16 + cq);
            cp_commit();
        }
        const float* Wc = Ws + cur*16*256;
        const float* Ac = As + cur*64*16;
        #pragma unroll
        for (int kk = 0; kk < 16; kk++) {
            float4 w0 = *(const float4*)(Wc + kk*256 + c0);
            float4 w1 = *(const float4*)(Wc + kk*256 + c1);
            #pragma unroll
            for (int r = 0; r < 8; r++) {
                float a = Ac[(wr + r)*16 + kk];
                acc[r][0] = fmaf(a, w0.x, acc[r][0]);
                acc[r][1] = fmaf(a, w0.y, acc[r][1]);
                acc[r][2] = fmaf(a, w0.z, acc[r][2]);
                acc[r][3] = fmaf(a, w0.w, acc[r][3]);
                acc[r][4] = fmaf(a, w1.x, acc[r][4]);
                acc[r][5] = fmaf(a, w1.y, acc[r][5]);
                acc[r][6] = fmaf(a, w1.z, acc[r][6]);
                acc[r][7] = fmaf(a, w1.w, acc[r][7]);
            }
        }
        if (kt < 15) cp_wait0();
        __syncthreads();
    }
    {
        float4 bv0 = *(const float4*)(b1 + c0), bv1 = *(const float4*)(b1 + c1);
        float4 gv0 = *(const float4*)(g1 + c0), gv1 = *(const float4*)(g1 + c1);
        float4 ev0 = *(const float4*)(be1 + c0), ev1 = *(const float4*)(be1 + c1);
        #pragma unroll
        for (int r = 0; r < 8; r++) {
            float v[8], o[8];
            v[0]=acc[r][0]+bv0.x; v[1]=acc[r][1]+bv0.y; v[2]=acc[r][2]+bv0.z; v[3]=acc[r][3]+bv0.w;
            v[4]=acc[r][4]+bv1.x; v[5]=acc[r][5]+bv1.y; v[6]=acc[r][6]+bv1.z; v[7]=acc[r][7]+bv1.w;
            ln_row(v, gv0, gv1, ev0, ev1, o);
            *(float4*)(Hs + (wr + r)*256 + c0) = make_float4(o[0],o[1],o[2],o[3]);
            *(float4*)(Hs + (wr + r)*256 + c1) = make_float4(o[4],o[5],o[6],o[7]);
        }
    }
    __syncthreads();
    #pragma unroll
    for (int r = 0; r < 8; r++)
        #pragma unroll
        for (int c = 0; c < 8; c++) acc[r][c] = 0.f;

    // ---------------- stage 2: e = LN(leaky(h@W2+b2)) ----------------
    #pragma unroll
    for (int i = 0; i < 4; i++)
        cp_async16(Ws + (tid + i*256)*4, W2 + (size_t)(tid + i*256)*4);
    cp_commit();
    cp_wait0();
    __syncthreads();

    for (int kt = 0; kt < 16; kt++) {
        const int cur = kt & 1, nxt = cur ^ 1;
        if (kt < 15) {
            const float* Wsrc = W2 + (size_t)(kt+1)*16*DD;
            float* Wdst = Ws + nxt*16*256;
            #pragma unroll
            for (int i = 0; i < 4; i++)
                cp_async16(Wdst + (tid + i*256)*4, Wsrc + (size_t)(tid + i*256)*4);
            cp_commit();
        }
        const float* Wc = Ws + cur*16*256;
        #pragma unroll
        for (int kk = 0; kk < 16; kk++) {
            float4 w0 = *(const float4*)(Wc + kk*256 + c0);
            float4 w1 = *(const float4*)(Wc + kk*256 + c1);
            #pragma unroll
            for (int r = 0; r < 8; r++) {
                float a = Hs[(wr + r)*256 + kt*16 + kk];
                acc[r][0] = fmaf(a, w0.x, acc[r][0]);
                acc[r][1] = fmaf(a, w0.y, acc[r][1]);
                acc[r][2] = fmaf(a, w0.z, acc[r][2]);
                acc[r][3] = fmaf(a, w0.w, acc[r][3]);
                acc[r][4] = fmaf(a, w1.x, acc[r][4]);
                acc[r][5] = fmaf(a, w1.y, acc[r][5]);
                acc[r][6] = fmaf(a, w1.z, acc[r][6]);
                acc[r][7] = fmaf(a, w1.w, acc[r][7]);
            }
        }
        if (kt < 15) cp_wait0();
        __syncthreads();
    }
    {
        float4 bv0 = *(const float4*)(b2 + c0), bv1 = *(const float4*)(b2 + c1);
        float4 gv0 = *(const float4*)(g2 + c0), gv1 = *(const float4*)(g2 + c1);
        float4 ev0 = *(const float4*)(be2 + c0), ev1 = *(const float4*)(be2 + c1);
        #pragma unroll
        for (int r = 0; r < 8; r++) {
            float v[8], o[8];
            v[0]=acc[r][0]+bv0.x; v[1]=acc[r][1]+bv0.y; v[2]=acc[r][2]+bv0.z; v[3]=acc[r][3]+bv0.w;
            v[4]=acc[r][4]+bv1.x; v[5]=acc[r][5]+bv1.y; v[6]=acc[r][6]+bv1.z; v[7]=acc[r][7]+bv1.w;
            ln_row(v, gv0, gv1, ev0, ev1, o);
            float ns = o[0]*o[0]+o[1]*o[1]+o[2]*o[2]+o[3]*o[3]
                     + o[4]*o[4]+o[5]*o[5]+o[6]*o[6]+o[7]*o[7];
            #pragma unroll
            for (int off = 16; off; off >>= 1)
                ns += __shfl_xor_sync(0xffffffffu, ns, off);
            size_t grow = (size_t)(row0 + wr + r);
            *(float4*)(E + grow*DD + c0) = make_float4(o[0],o[1],o[2],o[3]);
            *(float4*)(E + grow*DD + c1) = make_float4(o[4],o[5],o[6],o[7]);
            if (lane == 0) NRM[grow] = ns;
        }
    }
}

// cdist + cost_class + in/out loss + K(bf16), double-buffered (unchanged).
__global__ __launch_bounds__(256, 2)
void cost_kernel(const float* __restrict__ pa, const float* __restrict__ pb)
{
    __shared__ __align__(16) float Ast[2][16][132];
    __shared__ __align__(16) float Bst[2][16][132];
    __shared__ float redi[8], redo[8];

    const int b  = blockIdx.z;
    const int ti = blockIdx.y;
    const int tj = blockIdx.x;
    const int tid = threadIdx.x;
    const int ty = tid >> 4;
    const int tx = tid & 15;

    const float* Ab = g_eA + (size_t)b*NN*DD + (size_t)ti*128*DD;
    const float* Bb = g_eB + (size_t)b*NN*DD + (size_t)tj*128*DD;

    float acc[8][8];
    #pragma unroll
    for (int r = 0; r < 8; r++)
        #pragma unroll
        for (int c = 0; c < 8; c++) acc[r][c] = 0.f;

    float4 avr[2], bvr[2];
    #pragma unroll
    for (int s = 0; s < 2; s++) {
        int idx = tid + s*256;
        int row = idx >> 2, cq = (idx & 3) << 2;
        avr[s] = *(const float4*)(Ab + (size_t)row*DD + cq);
        bvr[s] = *(const float4*)(Bb + (size_t)row*DD + cq);
    }
    #pragma unroll
    for (int s = 0; s < 2; s++) {
        int idx = tid + s*256;
        int row = idx >> 2, cq = (idx & 3) << 2;
        Ast[0][cq+0][row]=avr[s].x; Ast[0][cq+1][row]=avr[s].y;
        Ast[0][cq+2][row]=avr[s].z; Ast[0][cq+3][row]=avr[s].w;
        Bst[0][cq+0][row]=bvr[s].x; Bst[0][cq+1][row]=bvr[s].y;
        Bst[0][cq+2][row]=bvr[s].z; Bst[0][cq+3][row]=bvr[s].w;
    }
    __syncthreads();

    for (int kt = 0; kt < 16; kt++) {
        const int cur = kt & 1, nxt = cur ^ 1;
        if (kt < 15) {
            #pragma unroll
            for (int s = 0; s < 2; s++) {
                int idx = tid + s*256;
                int row = idx >> 2, cq = (idx & 3) << 2;
                avr[s] = *(const float4*)(Ab + (size_t)row*DD + (kt+1)*16 + cq);
                bvr[s] = *(const float4*)(Bb + (size_t)row*DD + (kt+1)*16 + cq);
            }
        }
        #pragma unroll
        for (int kk = 0; kk < 16; kk++) {
            float4 a0 = *(const float4*)(&Ast[cur][kk][ty*4]);
            float4 a1 = *(const float4*)(&Ast[cur][kk][64 + ty*4]);
            float4 b0 = *(const float4*)(&Bst[cur][kk][tx*4]);
            float4 b1 = *(const float4*)(&Bst[cur][kk][64 + tx*4]);
            float ar[8] = {a0.x,a0.y,a0.z,a0.w,a1.x,a1.y,a1.z,a1.w};
            float br[8] = {b0.x,b0.y,b0.z,b0.w,b1.x,b1.y,b1.z,b1.w};
            #pragma unroll
            for (int r = 0; r < 8; r++)
                #pragma unroll
                for (int c = 0; c < 8; c++)
                    acc[r][c] = fmaf(ar[r], br[c], acc[r][c]);
        }
        if (kt < 15) {
            #pragma unroll
            for (int s = 0; s < 2; s++) {
                int idx = tid + s*256;
                int row = idx >> 2, cq = (idx & 3) << 2;
                Ast[nxt][cq+0][row]=avr[s].x; Ast[nxt][cq+1][row]=avr[s].y;
                Ast[nxt][cq+2][row]=avr[s].z; Ast[nxt][cq+3][row]=avr[s].w;
                Bst[nxt][cq+0][row]=bvr[s].x; Bst[nxt][cq+1][row]=bvr[s].y;
                Bst[nxt][cq+2][row]=bvr[s].z; Bst[nxt][cq+3][row]=bvr[s].w;
            }
        }
        __syncthreads();
    }

    float ni[8], pav[8]; int cai[8];
    float njv[8], pbv[8]; int cbj[8];
    #pragma unroll
    for (int r = 0; r < 8; r++) {
        int il = ti*128 + ((r < 4) ? ty*4 + r : 64 + ty*4 + (r-4));
        int gi = b*NN + il;
        ni[r] = g_nA[gi]; pav[r] = pa[gi]; cai[r] = g_cA[gi];
    }
    #pragma unroll
    for (int c = 0; c < 8; c++) {
        int jl = tj*128 + ((c < 4) ? tx*4 + c : 64 + tx*4 + (c-4));
        int gj = b*NN + jl;
        njv[c] = g_nB[gj]; pbv[c] = pb[gj]; cbj[c] = g_cB[gj];
    }

    float sin = 0.f, sout = 0.f;
    #pragma unroll
    for (int r = 0; r < 8; r++) {
        int il = ti*128 + ((r < 4) ? ty*4 + r : 64 + ty*4 + (r-4));
        size_t rowb = ((size_t)(b*NN + il)) * NN;
        #pragma unroll
        for (int cg = 0; cg < 2; cg++) {
            float kv[4];
            #pragma unroll
            for (int c4 = 0; c4 < 4; c4++) {
                int c = cg*4 + c4;
                float sq   = ni[r] + njv[c] - 2.f*acc[r][c];
                float cost = sqrtf(fmaxf(sq, 0.f));
                float pm   = pav[r]*pbv[c];
                float cc   = cost + (BIGC - BIGC*pm);
                float w    = cc * pm;
                if (cai[r] == cbj[c]) sin += w; else sout += w;
                kv[c4] = __expf(-2.f*cc);
            }
            uint2 pk;
            pk.x = pack_bf2(kv[0], kv[1]);
            pk.y = pack_bf2(kv[2], kv[3]);
            *(uint2*)(g_K + rowb + tj*128 + cg*64 + tx*4) = pk;
        }
    }
    #pragma unroll
    for (int off = 16; off; off >>= 1) {
        sin  += __shfl_xor_sync(0xffffffffu, sin,  off);
        sout += __shfl_xor_sync(0xffffffffu, sout, off);
    }
    int lane = tid & 31, warp = tid >> 5;
    if (lane == 0) { redi[warp] = sin; redo[warp] = sout; }
    __syncthreads();
    if (tid == 0) {
        float a = 0.f, o2 = 0.f;
        #pragma unroll
        for (int w = 0; w < 8; w++) { a += redi[w]; o2 += redo[w]; }
        atomicAdd(&g_acc[0], (double)a);
        atomicAdd(&g_acc[1], (double)o2);
    }
}

// Sinkhorn + fused sup loss. 1 CTA (1024 threads) per batch (unchanged).
__global__ __launch_bounds__(1024)
void sinkhorn_kernel(const float* __restrict__ rel, const float* __restrict__ pa)
{
    __shared__ __align__(16) float su[NN];
    __shared__ __align__(16) float sv[NN];
    __shared__ __align__(16) float part[8][NN];
    __shared__ float sred[32];

    const int b = blockIdx.x;
    const __nv_bfloat16* Kb = g_K + (size_t)b*NN*NN;
    const int tid  = threadIdx.x;
    const int lane = tid & 31;
    const int warp = tid >> 5;
    const int grp  = tid >> 7;
    const int jc   = (tid & 127) * 4;

    if (tid < NN) su[tid] = 1.f/512.f;
    __syncthreads();

    for (int it = 0; it < 10; it++) {
        float a0 = 0.f, a1 = 0.f, a2 = 0.f, a3 = 0.f;
        const int i0 = grp * 64;
        const uint2* K2 = (const uint2*)Kb;
        #pragma unroll 8
        for (int i = 0; i < 64; i++) {
            uint2 kq = K2[(((size_t)(i0 + i))*NN + jc) >> 2];
            float k0,k1,k2,k3;
            unpack_bf2(kq.x, k0, k1);
            unpack_bf2(kq.y, k2, k3);
            float ui = su[i0 + i];
            a0 = fmaf(k0, ui, a0);
            a1 = fmaf(k1, ui, a1);
            a2 = fmaf(k2, ui, a2);
            a3 = fmaf(k3, ui, a3);
        }
        *(float4*)(&part[grp][jc]) = make_float4(a0,a1,a2,a3);
        __syncthreads();
        if (tid < NN) {
            float y = part[0][tid] + part[1][tid] + part[2][tid] + part[3][tid]
                    + part[4][tid] + part[5][tid] + part[6][tid] + part[7][tid];
            sv[tid] = (1.f/512.f) / y;
        }
        __syncthreads();
        for (int rr = 0; rr < 16; rr++) {
            int i = warp*16 + rr;
            const uint4* kr = (const uint4*)(Kb + (size_t)i*NN);
            uint4 q0 = kr[lane*2];
            uint4 q1 = kr[lane*2 + 1];
            float s = 0.f;
            float k0,k1;
            float4 vv;
            vv = *(const float4*)(sv + lane*16 + 0);
            unpack_bf2(q0.x, k0, k1); s = fmaf(k0, vv.x, s); s = fmaf(k1, vv.y, s);
            unpack_bf2(q0.y, k0, k1); s = fmaf(k0, vv.z, s); s = fmaf(k1, vv.w, s);
            vv = *(const float4*)(sv + lane*16 + 4);
            unpack_bf2(q0.z, k0, k1); s = fmaf(k0, vv.x, s); s = fmaf(k1, vv.y, s);
            unpack_bf2(q0.w, k0, k1); s = fmaf(k0, vv.z, s); s = fmaf(k1, vv.w, s);
            vv = *(const float4*)(sv + lane*16 + 8);
            unpack_bf2(q1.x, k0, k1); s = fmaf(k0, vv.x, s); s = fmaf(k1, vv.y, s);
            unpack_bf2(q1.y, k0, k1); s = fmaf(k0, vv.z, s); s = fmaf(k1, vv.w, s);
            vv = *(const float4*)(sv + lane*16 + 12);
            unpack_bf2(q1.z, k0, k1); s = fmaf(k0, vv.x, s); s = fmaf(k1, vv.y, s);
            unpack_bf2(q1.w, k0, k1); s = fmaf(k0, vv.z, s); s = fmaf(k1, vv.w, s);
            #pragma unroll
            for (int off = 16; off; off >>= 1)
                s += __shfl_xor_sync(0xffffffffu, s, off);
            if (lane == 0) su[i] = (1.f/512.f) / s;
        }
        __syncthreads();
    }

    const float* relb = rel + (size_t)b*NN*NN;
    float lacc = 0.f;
    for (int t = 0; t < 32; t++) {
        int idx = tid + t*1024;
        int e = idx * 8;
        int i = e >> 9;
        int j = e & 511;
        uint4 kq = ((const uint4*)Kb)[idx];
        float kf[8];
        unpack_bf2(kq.x, kf[0], kf[1]);
        unpack_bf2(kq.y, kf[2], kf[3]);
        unpack_bf2(kq.z, kf[4], kf[5]);
        unpack_bf2(kq.w, kf[6], kf[7]);
        float4 rv0 = *(const float4*)(relb + e);
        float4 rv1 = *(const float4*)(relb + e + 4);
        float ui  = su[i] * 512.f;
        float pai = pa[b*NN + i];
        float4 vv0 = *(const float4*)(sv + j);
        float4 vv1 = *(const float4*)(sv + j + 4);
        float d0 = ui*kf[0]*vv0.x - rv0.x;
        float d1 = ui*kf[1]*vv0.y - rv0.y;
        float d2 = ui*kf[2]*vv0.z - rv0.z;
        float d3 = ui*kf[3]*vv0.w - rv0.w;
        float d4 = ui*kf[4]*vv1.x - rv1.x;
        float d5 = ui*kf[5]*vv1.y - rv1.y;
        float d6 = ui*kf[6]*vv1.z - rv1.z;
        float d7 = ui*kf[7]*vv1.w - rv1.w;
        lacc += pai * (d0*d0 + d1*d1 + d2*d2 + d3*d3
                     + d4*d4 + d5*d5 + d6*d6 + d7*d7);
    }
    #pragma unroll
    for (int off = 16; off; off >>= 1)
        lacc += __shfl_xor_sync(0xffffffffu, lacc, off);
    if (lane == 0) sred[warp] = lacc;
    __syncthreads();
    if (tid == 0) {
        float s = 0.f;
        #pragma unroll
        for (int w = 0; w < 32; w++) s += sred[w];
        atomicAdd(&g_acc[2], (double)s);
    }
}

__global__ void finalize_kernel(const float* __restrict__ pa, float* __restrict__ out)
{
    __shared__ float red[256];
    float s = 0.f;
    for (int i = threadIdx.x; i < BSZ*NN; i += 256) s += pa[i];
    red[threadIdx.x] = s;
    __syncthreads();
    for (int off = 128; off; off >>= 1) {
        if (threadIdx.x < off) red[threadIdx.x] += red[threadIdx.x + off];
        __syncthreads();
    }
    if (threadIdx.x == 0) {
        double M = (double)BSZ * (double)NN * (double)NN;
        out[0] = (float)(g_acc[0]/M - g_acc[1]/M + 10.0*(g_acc[2]/(double)red[0]));
    }
}

extern "C" void kernel_launch(void* const* d_in, const int* in_sizes, int n_in,
                              void* d_out, int out_size)
{
    const float* la  = (const float*)d_in[0];
    const float* lb  = (const float*)d_in[1];
    const float* xA  = (const float*)d_in[2];
    const float* xB  = (const float*)d_in[3];
    const float* rel = (const float*)d_in[4];
    const float* pa  = (const float*)d_in[5];
    const float* pb  = (const float*)d_in[6];
    const float* W1  = (const float*)d_in[7];
    const float* b1  = (const float*)d_in[8];
    const float* g1  = (const float*)d_in[9];
    const float* be1 = (const float*)d_in[10];
    const float* W2  = (const float*)d_in[11];
    const float* b2  = (const float*)d_in[12];
    const float* g2  = (const float*)d_in[13];
    const float* be2 = (const float*)d_in[14];
    float* out = (float*)d_out;

    cudaFuncSetAttribute(embed_kernel,
                         cudaFuncAttributeMaxDynamicSharedMemorySize, EMBED_SMEM);

    zero_acc_kernel<<<1, 32>>>();
    class_argmax_kernel<<<(BSZ*NN + 255)/256, 256>>>(la, lb);
    embed_kernel<<<dim3(BSZ*NN/64, 2), 256, EMBED_SMEM>>>(
        xA, xB, W1, b1, g1, be1, W2, b2, g2, be2);
    cost_kernel<<<dim3(4, 4, BSZ), 256>>>(pa, pb);
    sinkhorn_kernel<<<BSZ, 1024>>>(rel, pa);
    finalize_kernel<<<1, 256>>>(pa, out);
}

// round 8
// speedup vs baseline: 1.9563x; 1.4228x over previous
#include <cuda_runtime.h>
#include <cuda_bf16.h>
#include <stdint.h>
#include <math.h>

#define BSZ 64
#define NN 512
#define DD 256
#define BIGC 1.0e9f

__device__ float g_eA[BSZ*NN*DD];
__device__ float g_eB[BSZ*NN*DD];
__device__ float g_nA[BSZ*NN];
__device__ float g_nB[BSZ*NN];
__device__ __nv_bfloat16 g_K[(size_t)BSZ*NN*NN];
__device__ int   g_cA[BSZ*NN];
__device__ int   g_cB[BSZ*NN];
__device__ double g_acc[3];

// ---- helpers ----
__device__ __forceinline__ uint32_t pack_bf2(float a, float b) {
    __nv_bfloat162 h = __floats2bfloat162_rn(a, b);
    return *reinterpret_cast<uint32_t*>(&h);
}
__device__ __forceinline__ void unpack_bf2(uint32_t u, float& a, float& b) {
    a = __uint_as_float(u << 16);
    b = __uint_as_float(u & 0xffff0000u);
}
__device__ __forceinline__ void cp_async16(void* smem_dst, const void* gmem_src) {
    uint32_t s = (uint32_t)__cvta_generic_to_shared(smem_dst);
    asm volatile("cp.async.cg.shared.global [%0], [%1], 16;" :: "r"(s), "l"(gmem_src));
}
__device__ __forceinline__ void cp_commit() {
    asm volatile("cp.async.commit_group;");
}
__device__ __forceinline__ void cp_wait0() {
    asm volatile("cp.async.wait_group 0;");
}
__device__ __forceinline__ void mma_tf32(float* c,
    uint32_t a0, uint32_t a1, uint32_t a2, uint32_t a3,
    uint32_t b0, uint32_t b1)
{
    asm volatile(
        "mma.sync.aligned.m16n8k8.row.col.f32.tf32.tf32.f32 "
        "{%0,%1,%2,%3}, {%4,%5,%6,%7}, {%8,%9}, {%0,%1,%2,%3};"
        : "+f"(c[0]), "+f"(c[1]), "+f"(c[2]), "+f"(c[3])
        : "r"(a0), "r"(a1), "r"(a2), "r"(a3), "r"(b0), "r"(b1));
}

__global__ void zero_acc_kernel() {
    if (threadIdx.x < 3) g_acc[threadIdx.x] = 0.0;
}

__global__ void class_argmax_kernel(const float* __restrict__ la,
                                    const float* __restrict__ lb) {
    int t = blockIdx.x * blockDim.x + threadIdx.x;
    if (t >= BSZ*NN) return;
    float4 a = ((const float4*)la)[t];
    int ba = 0; float bv = a.x;
    if (a.y > bv) { bv = a.y; ba = 1; }
    if (a.z > bv) { bv = a.z; ba = 2; }
    if (a.w > bv) { bv = a.w; ba = 3; }
    g_cA[t] = ba;
    float4 b = ((const float4*)lb)[t];
    int bb = 0; bv = b.x;
    if (b.y > bv) { bv = b.y; bb = 1; }
    if (b.z > bv) { bv = b.z; bb = 2; }
    if (b.w > bv) { bv = b.w; bb = 3; }
    g_cB[t] = bb;
}

__device__ __forceinline__ void ln_row(float v[8],
    const float4& g0, const float4& g1, const float4& e0, const float4& e1,
    float* o)
{
    float s = 0.f, sq = 0.f;
    #pragma unroll
    for (int j = 0; j < 8; j++) {
        v[j] = v[j] > 0.f ? v[j] : 0.01f * v[j];
        s += v[j]; sq += v[j]*v[j];
    }
    #pragma unroll
    for (int off = 16; off; off >>= 1) {
        s  += __shfl_xor_sync(0xffffffffu, s, off);
        sq += __shfl_xor_sync(0xffffffffu, sq, off);
    }
    float mean = s * (1.f/256.f);
    float var  = sq * (1.f/256.f) - mean*mean;
    float rstd = rsqrtf(var + 1e-5f);
    o[0] = (v[0]-mean)*rstd*g0.x + e0.x;
    o[1] = (v[1]-mean)*rstd*g0.y + e0.y;
    o[2] = (v[2]-mean)*rstd*g0.z + e0.z;
    o[3] = (v[3]-mean)*rstd*g0.w + e0.w;
    o[4] = (v[4]-mean)*rstd*g1.x + e1.x;
    o[5] = (v[5]-mean)*rstd*g1.y + e1.y;
    o[6] = (v[6]-mean)*rstd*g1.z + e1.z;
    o[7] = (v[7]-mean)*rstd*g1.w + e1.w;
}

// Fused 2-layer MLP+LN embed with tf32 mma.sync tensor cores.
// Block: 256 thr (8 warps) -> 64 rows x 256 cols.
// Warp w: rows [(w&3)*16, +16), cols [(w>>2)*128, +128); 16 m16n8k8 C-frags.
// Swizzles: Ws (k,n)->n^((k&3)<<3); Xs (r,k)->k^(((r>>1)&3)<<2); Hs (r,c)->c^((r&7)<<2).
#define EMBED_SMEM ((64*256 + 2*16*256 + 2*64*16) * 4)

__global__ __launch_bounds__(256, 2)
void embed_kernel(const float* __restrict__ xA, const float* __restrict__ xB,
                  const float* __restrict__ W1, const float* __restrict__ b1,
                  const float* __restrict__ g1, const float* __restrict__ be1,
                  const float* __restrict__ W2, const float* __restrict__ b2,
                  const float* __restrict__ g2, const float* __restrict__ be2)
{
    extern __shared__ float sm[];
    float* Hs = sm;                  // 64*256 (swizzled)
    float* Ws = sm + 64*256;         // 2 x 16*256 (swizzled)
    float* Xs = Ws + 2*16*256;       // 2 x 64*16 (swizzled)

    const float* X  = blockIdx.y ? xB   : xA;
    float* E        = blockIdx.y ? g_eB : g_eA;
    float* NRM      = blockIdx.y ? g_nB : g_nA;

    const int tid  = threadIdx.x;
    const int lane = tid & 31;
    const int warp = tid >> 5;
    const int wm   = warp & 3;      // row group
    const int wn   = warp >> 2;     // col group
    const int g    = lane >> 2;     // 0..7
    const int t    = lane & 3;      // 0..3
    const int row0 = blockIdx.x * 64;

    // cp.async index precompute
    const int xr = tid >> 2, xkq = (tid & 3) << 2;
    const int xdst = xr*16 + (xkq ^ (((xr>>1)&3)<<2));

    float c[16][4];
    #pragma unroll
    for (int j = 0; j < 16; j++)
        #pragma unroll
        for (int q = 0; q < 4; q++) c[j][q] = 0.f;

    // ---------------- stage 1: pre1 = x @ W1 ----------------
    {   // prologue tile 0 -> buf 0
        #pragma unroll
        for (int i = 0; i < 4; i++) {
            int f = tid + i*256;
            int k = f >> 6, n4 = (f & 63) << 2;
            cp_async16(Ws + k*256 + (n4 ^ ((k&3)<<3)), W1 + (size_t)k*256 + n4);
        }
        cp_async16(Xs + xdst, X + (size_t)(row0 + xr)*DD + xkq);
        cp_commit(); cp_wait0();
    }
    __syncthreads();

    for (int kt = 0; kt < 16; kt++) {
        const int cur = kt & 1, nxt = cur ^ 1;
        if (kt < 15) {
            const float* Wsrc = W1 + (size_t)(kt+1)*16*DD;
            float* Wdst = Ws + nxt*4096;
            #pragma unroll
            for (int i = 0; i < 4; i++) {
                int f = tid + i*256;
                int k = f >> 6, n4 = (f & 63) << 2;
                cp_async16(Wdst + k*256 + (n4 ^ ((k&3)<<3)), Wsrc + (size_t)k*256 + n4);
            }
            cp_async16(Xs + nxt*1024 + xdst,
                       X + (size_t)(row0 + xr)*DD + (kt+1)*16 + xkq);
            cp_commit();
        }
        const float* Wc = Ws + cur*4096;
        const float* Xc = Xs + cur*1024;
        const int sA = ((g>>1)&3) << 2;
        const int sB = t << 3;
        #pragma unroll
        for (int h = 0; h < 2; h++) {
            int kl = h*8 + t;
            uint32_t a0 = __float_as_uint(Xc[(wm*16+g  )*16 + ((kl  ) ^ sA)]);
            uint32_t a1 = __float_as_uint(Xc[(wm*16+g+8)*16 + ((kl  ) ^ sA)]);
            uint32_t a2 = __float_as_uint(Xc[(wm*16+g  )*16 + ((kl+4) ^ sA)]);
            uint32_t a3 = __float_as_uint(Xc[(wm*16+g+8)*16 + ((kl+4) ^ sA)]);
            const float* Wr0 = Wc + (kl  )*256;
            const float* Wr1 = Wc + (kl+4)*256;
            #pragma unroll
            for (int j = 0; j < 16; j++) {
                int n = wn*128 + j*8 + g;
                uint32_t b0 = __float_as_uint(Wr0[n ^ sB]);
                uint32_t b1 = __float_as_uint(Wr1[n ^ sB]);
                mma_tf32(c[j], a0, a1, a2, a3, b0, b1);
            }
        }
        if (kt < 15) cp_wait0();
        __syncthreads();
    }

    // stage-2 W prologue overlaps the LN pass below
    {
        #pragma unroll
        for (int i = 0; i < 4; i++) {
            int f = tid + i*256;
            int k = f >> 6, n4 = (f & 63) << 2;
            cp_async16(Ws + k*256 + (n4 ^ ((k&3)<<3)), W2 + (size_t)k*256 + n4);
        }
        cp_commit();
    }

    // write raw pre-act frags to Hs (swizzled)
    #pragma unroll
    for (int j = 0; j < 16; j++) {
        int r  = wm*16 + g;
        int cc = wn*128 + j*8 + 2*t;
        *(float2*)&Hs[r*256 + (cc ^ ((r&7)<<2))] = make_float2(c[j][0], c[j][1]);
        int r2 = r + 8;
        *(float2*)&Hs[r2*256 + (cc ^ ((r2&7)<<2))] = make_float2(c[j][2], c[j][3]);
    }
    __syncthreads();

    // LN pass 1: warp owns rows warp*8..+7; lane cols lane*4 & 128+lane*4
    {
        const int c0 = lane*4, c1 = 128 + lane*4;
        float4 bv0 = *(const float4*)(b1 + c0), bv1 = *(const float4*)(b1 + c1);
        float4 gv0 = *(const float4*)(g1 + c0), gv1 = *(const float4*)(g1 + c1);
        float4 ev0 = *(const float4*)(be1 + c0), ev1 = *(const float4*)(be1 + c1);
        #pragma unroll
        for (int r = 0; r < 8; r++) {
            int row = warp*8 + r;
            int sH = (row & 7) << 2;
            float4 x0 = *(const float4*)&Hs[row*256 + (c0 ^ sH)];
            float4 x1 = *(const float4*)&Hs[row*256 + (c1 ^ sH)];
            float v[8], o[8];
            v[0]=x0.x+bv0.x; v[1]=x0.y+bv0.y; v[2]=x0.z+bv0.z; v[3]=x0.w+bv0.w;
            v[4]=x1.x+bv1.x; v[5]=x1.y+bv1.y; v[6]=x1.z+bv1.z; v[7]=x1.w+bv1.w;
            ln_row(v, gv0, gv1, ev0, ev1, o);
            *(float4*)&Hs[row*256 + (c0 ^ sH)] = make_float4(o[0],o[1],o[2],o[3]);
            *(float4*)&Hs[row*256 + (c1 ^ sH)] = make_float4(o[4],o[5],o[6],o[7]);
        }
    }
    cp_wait0();
    __syncthreads();

    // ---------------- stage 2: pre2 = h @ W2 ----------------
    #pragma unroll
    for (int j = 0; j < 16; j++)
        #pragma unroll
        for (int q = 0; q < 4; q++) c[j][q] = 0.f;

    for (int kt = 0; kt < 16; kt++) {
        const int cur = kt & 1, nxt = cur ^ 1;
        if (kt < 15) {
            const float* Wsrc = W2 + (size_t)(kt+1)*16*DD;
            float* Wdst = Ws + nxt*4096;
            #pragma unroll
            for (int i = 0; i < 4; i++) {
                int f = tid + i*256;
                int k = f >> 6, n4 = (f & 63) << 2;
                cp_async16(Wdst + k*256 + (n4 ^ ((k&3)<<3)), Wsrc + (size_t)k*256 + n4);
            }
            cp_commit();
        }
        const float* Wc = Ws + cur*4096;
        const float* H0 = Hs + (wm*16 + g  )*256;
        const float* H1 = Hs + (wm*16 + g+8)*256;
        const int sH = g << 2;
        const int sB = t << 3;
        #pragma unroll
        for (int h = 0; h < 2; h++) {
            int k = kt*16 + h*8;
            uint32_t a0 = __float_as_uint(H0[(k+t  ) ^ sH]);
            uint32_t a1 = __float_as_uint(H1[(k+t  ) ^ sH]);
            uint32_t a2 = __float_as_uint(H0[(k+t+4) ^ sH]);
            uint32_t a3 = __float_as_uint(H1[(k+t+4) ^ sH]);
            const float* Wr0 = Wc + (h*8+t  )*256;
            const float* Wr1 = Wc + (h*8+t+4)*256;
            #pragma unroll
            for (int j = 0; j < 16; j++) {
                int n = wn*128 + j*8 + g;
                uint32_t b0 = __float_as_uint(Wr0[n ^ sB]);
                uint32_t b1 = __float_as_uint(Wr1[n ^ sB]);
                mma_tf32(c[j], a0, a1, a2, a3, b0, b1);
            }
        }
        if (kt < 15) cp_wait0();
        __syncthreads();
    }

    // write raw pre-act frags to Hs (swizzled)
    #pragma unroll
    for (int j = 0; j < 16; j++) {
        int r  = wm*16 + g;
        int cc = wn*128 + j*8 + 2*t;
        *(float2*)&Hs[r*256 + (cc ^ ((r&7)<<2))] = make_float2(c[j][0], c[j][1]);
        int r2 = r + 8;
        *(float2*)&Hs[r2*256 + (cc ^ ((r2&7)<<2))] = make_float2(c[j][2], c[j][3]);
    }
    __syncthreads();

    // LN pass 2 + store to gmem
    {
        const int c0 = lane*4, c1 = 128 + lane*4;
        float4 bv0 = *(const float4*)(b2 + c0), bv1 = *(const float4*)(b2 + c1);
        float4 gv0 = *(const float4*)(g2 + c0), gv1 = *(const float4*)(g2 + c1);
        float4 ev0 = *(const float4*)(be2 + c0), ev1 = *(const float4*)(be2 + c1);
        #pragma unroll
        for (int r = 0; r < 8; r++) {
            int row = warp*8 + r;
            int sH = (row & 7) << 2;
            float4 x0 = *(const float4*)&Hs[row*256 + (c0 ^ sH)];
            float4 x1 = *(const float4*)&Hs[row*256 + (c1 ^ sH)];
            float v[8], o[8];
            v[0]=x0.x+bv0.x; v[1]=x0.y+bv0.y; v[2]=x0.z+bv0.z; v[3]=x0.w+bv0.w;
            v[4]=x1.x+bv1.x; v[5]=x1.y+bv1.y; v[6]=x1.z+bv1.z; v[7]=x1.w+bv1.w;
            ln_row(v, gv0, gv1, ev0, ev1, o);
            float ns = o[0]*o[0]+o[1]*o[1]+o[2]*o[2]+o[3]*o[3]
                     + o[4]*o[4]+o[5]*o[5]+o[6]*o[6]+o[7]*o[7];
            #pragma unroll
            for (int off = 16; off; off >>= 1)
                ns += __shfl_xor_sync(0xffffffffu, ns, off);
            size_t grow = (size_t)(row0 + row);
            *(float4*)(E + grow*DD + c0) = make_float4(o[0],o[1],o[2],o[3]);
            *(float4*)(E + grow*DD + c1) = make_float4(o[4],o[5],o[6],o[7]);
            if (lane == 0) NRM[grow] = ns;
        }
    }
}

// cdist + cost_class + in/out loss + K(bf16), double-buffered (unchanged).
__global__ __launch_bounds__(256, 2)
void cost_kernel(const float* __restrict__ pa, const float* __restrict__ pb)
{
    __shared__ __align__(16) float Ast[2][16][132];
    __shared__ __align__(16) float Bst[2][16][132];
    __shared__ float redi[8], redo[8];

    const int b  = blockIdx.z;
    const int ti = blockIdx.y;
    const int tj = blockIdx.x;
    const int tid = threadIdx.x;
    const int ty = tid >> 4;
    const int tx = tid & 15;

    const float* Ab = g_eA + (size_t)b*NN*DD + (size_t)ti*128*DD;
    const float* Bb = g_eB + (size_t)b*NN*DD + (size_t)tj*128*DD;

    float acc[8][8];
    #pragma unroll
    for (int r = 0; r < 8; r++)
        #pragma unroll
        for (int c = 0; c < 8; c++) acc[r][c] = 0.f;

    float4 avr[2], bvr[2];
    #pragma unroll
    for (int s = 0; s < 2; s++) {
        int idx = tid + s*256;
        int row = idx >> 2, cq = (idx & 3) << 2;
        avr[s] = *(const float4*)(Ab + (size_t)row*DD + cq);
        bvr[s] = *(const float4*)(Bb + (size_t)row*DD + cq);
    }
    #pragma unroll
    for (int s = 0; s < 2; s++) {
        int idx = tid + s*256;
        int row = idx >> 2, cq = (idx & 3) << 2;
        Ast[0][cq+0][row]=avr[s].x; Ast[0][cq+1][row]=avr[s].y;
        Ast[0][cq+2][row]=avr[s].z; Ast[0][cq+3][row]=avr[s].w;
        Bst[0][cq+0][row]=bvr[s].x; Bst[0][cq+1][row]=bvr[s].y;
        Bst[0][cq+2][row]=bvr[s].z; Bst[0][cq+3][row]=bvr[s].w;
    }
    __syncthreads();

    for (int kt = 0; kt < 16; kt++) {
        const int cur = kt & 1, nxt = cur ^ 1;
        if (kt < 15) {
            #pragma unroll
            for (int s = 0; s < 2; s++) {
                int idx = tid + s*256;
                int row = idx >> 2, cq = (idx & 3) << 2;
                avr[s] = *(const float4*)(Ab + (size_t)row*DD + (kt+1)*16 + cq);
                bvr[s] = *(const float4*)(Bb + (size_t)row*DD + (kt+1)*16 + cq);
            }
        }
        #pragma unroll
        for (int kk = 0; kk < 16; kk++) {
            float4 a0 = *(const float4*)(&Ast[cur][kk][ty*4]);
            float4 a1 = *(const float4*)(&Ast[cur][kk][64 + ty*4]);
            float4 b0 = *(const float4*)(&Bst[cur][kk][tx*4]);
            float4 b1 = *(const float4*)(&Bst[cur][kk][64 + tx*4]);
            float ar[8] = {a0.x,a0.y,a0.z,a0.w,a1.x,a1.y,a1.z,a1.w};
            float br[8] = {b0.x,b0.y,b0.z,b0.w,b1.x,b1.y,b1.z,b1.w};
            #pragma unroll
            for (int r = 0; r < 8; r++)
                #pragma unroll
                for (int c = 0; c < 8; c++)
                    acc[r][c] = fmaf(ar[r], br[c], acc[r][c]);
        }
        if (kt < 15) {
            #pragma unroll
            for (int s = 0; s < 2; s++) {
                int idx = tid + s*256;
                int row = idx >> 2, cq = (idx & 3) << 2;
                Ast[nxt][cq+0][row]=avr[s].x; Ast[nxt][cq+1][row]=avr[s].y;
                Ast[nxt][cq+2][row]=avr[s].z; Ast[nxt][cq+3][row]=avr[s].w;
                Bst[nxt][cq+0][row]=bvr[s].x; Bst[nxt][cq+1][row]=bvr[s].y;
                Bst[nxt][cq+2][row]=bvr[s].z; Bst[nxt][cq+3][row]=bvr[s].w;
            }
        }
        __syncthreads();
    }

    float ni[8], pav[8]; int cai[8];
    float njv[8], pbv[8]; int cbj[8];
    #pragma unroll
    for (int r = 0; r < 8; r++) {
        int il = ti*128 + ((r < 4) ? ty*4 + r : 64 + ty*4 + (r-4));
        int gi = b*NN + il;
        ni[r] = g_nA[gi]; pav[r] = pa[gi]; cai[r] = g_cA[gi];
    }
    #pragma unroll
    for (int c = 0; c < 8; c++) {
        int jl = tj*128 + ((c < 4) ? tx*4 + c : 64 + tx*4 + (c-4));
        int gj = b*NN + jl;
        njv[c] = g_nB[gj]; pbv[c] = pb[gj]; cbj[c] = g_cB[gj];
    }

    float sin = 0.f, sout = 0.f;
    #pragma unroll
    for (int r = 0; r < 8; r++) {
        int il = ti*128 + ((r < 4) ? ty*4 + r : 64 + ty*4 + (r-4));
        size_t rowb = ((size_t)(b*NN + il)) * NN;
        #pragma unroll
        for (int cg = 0; cg < 2; cg++) {
            float kv[4];
            #pragma unroll
            for (int c4 = 0; c4 < 4; c4++) {
                int c = cg*4 + c4;
                float sq   = ni[r] + njv[c] - 2.f*acc[r][c];
                float cost = sqrtf(fmaxf(sq, 0.f));
                float pm   = pav[r]*pbv[c];
                float cc   = cost + (BIGC - BIGC*pm);
                float w    = cc * pm;
                if (cai[r] == cbj[c]) sin += w; else sout += w;
                kv[c4] = __expf(-2.f*cc);
            }
            uint2 pk;
            pk.x = pack_bf2(kv[0], kv[1]);
            pk.y = pack_bf2(kv[2], kv[3]);
            *(uint2*)(g_K + rowb + tj*128 + cg*64 + tx*4) = pk;
        }
    }
    #pragma unroll
    for (int off = 16; off; off >>= 1) {
        sin  += __shfl_xor_sync(0xffffffffu, sin,  off);
        sout += __shfl_xor_sync(0xffffffffu, sout, off);
    }
    int lane = tid & 31, warp = tid >> 5;
    if (lane == 0) { redi[warp] = sin; redo[warp] = sout; }
    __syncthreads();
    if (tid == 0) {
        float a = 0.f, o2 = 0.f;
        #pragma unroll
        for (int w = 0; w < 8; w++) { a += redi[w]; o2 += redo[w]; }
        atomicAdd(&g_acc[0], (double)a);
        atomicAdd(&g_acc[1], (double)o2);
    }
}

// Sinkhorn + fused sup loss. 1 CTA (1024 threads) per batch (unchanged).
__global__ __launch_bounds__(1024)
void sinkhorn_kernel(const float* __restrict__ rel, const float* __restrict__ pa)
{
    __shared__ __align__(16) float su[NN];
    __shared__ __align__(16) float sv[NN];
    __shared__ __align__(16) float part[8][NN];
    __shared__ float sred[32];

    const int b = blockIdx.x;
    const __nv_bfloat16* Kb = g_K + (size_t)b*NN*NN;
    const int tid  = threadIdx.x;
    const int lane = tid & 31;
    const int warp = tid >> 5;
    const int grp  = tid >> 7;
    const int jc   = (tid & 127) * 4;

    if (tid < NN) su[tid] = 1.f/512.f;
    __syncthreads();

    for (int it = 0; it < 10; it++) {
        float a0 = 0.f, a1 = 0.f, a2 = 0.f, a3 = 0.f;
        const int i0 = grp * 64;
        const uint2* K2 = (const uint2*)Kb;
        #pragma unroll 8
        for (int i = 0; i < 64; i++) {
            uint2 kq = K2[(((size_t)(i0 + i))*NN + jc) >> 2];
            float k0,k1,k2,k3;
            unpack_bf2(kq.x, k0, k1);
            unpack_bf2(kq.y, k2, k3);
            float ui = su[i0 + i];
            a0 = fmaf(k0, ui, a0);
            a1 = fmaf(k1, ui, a1);
            a2 = fmaf(k2, ui, a2);
            a3 = fmaf(k3, ui, a3);
        }
        *(float4*)(&part[grp][jc]) = make_float4(a0,a1,a2,a3);
        __syncthreads();
        if (tid < NN) {
            float y = part[0][tid] + part[1][tid] + part[2][tid] + part[3][tid]
                    + part[4][tid] + part[5][tid] + part[6][tid] + part[7][tid];
            sv[tid] = (1.f/512.f) / y;
        }
        __syncthreads();
        for (int rr = 0; rr < 16; rr++) {
            int i = warp*16 + rr;
            const uint4* kr = (const uint4*)(Kb + (size_t)i*NN);
            uint4 q0 = kr[lane*2];
            uint4 q1 = kr[lane*2 + 1];
            float s = 0.f;
            float k0,k1;
            float4 vv;
            vv = *(const float4*)(sv + lane*16 + 0);
            unpack_bf2(q0.x, k0, k1); s = fmaf(k0, vv.x, s); s = fmaf(k1, vv.y, s);
            unpack_bf2(q0.y, k0, k1); s = fmaf(k0, vv.z, s); s = fmaf(k1, vv.w, s);
            vv = *(const float4*)(sv + lane*16 + 4);
            unpack_bf2(q0.z, k0, k1); s = fmaf(k0, vv.x, s); s = fmaf(k1, vv.y, s);
            unpack_bf2(q0.w, k0, k1); s = fmaf(k0, vv.z, s); s = fmaf(k1, vv.w, s);
            vv = *(const float4*)(sv + lane*16 + 8);
            unpack_bf2(q1.x, k0, k1); s = fmaf(k0, vv.x, s); s = fmaf(k1, vv.y, s);
            unpack_bf2(q1.y, k0, k1); s = fmaf(k0, vv.z, s); s = fmaf(k1, vv.w, s);
            vv = *(const float4*)(sv + lane*16 + 12);
            unpack_bf2(q1.z, k0, k1); s = fmaf(k0, vv.x, s); s = fmaf(k1, vv.y, s);
            unpack_bf2(q1.w, k0, k1); s = fmaf(k0, vv.z, s); s = fmaf(k1, vv.w, s);
            #pragma unroll
            for (int off = 16; off; off >>= 1)
                s += __shfl_xor_sync(0xffffffffu, s, off);
            if (lane == 0) su[i] = (1.f/512.f) / s;
        }
        __syncthreads();
    }

    const float* relb = rel + (size_t)b*NN*NN;
    float lacc = 0.f;
    for (int t = 0; t < 32; t++) {
        int idx = tid + t*1024;
        int e = idx * 8;
        int i = e >> 9;
        int j = e & 511;
        uint4 kq = ((const uint4*)Kb)[idx];
        float kf[8];
        unpack_bf2(kq.x, kf[0], kf[1]);
        unpack_bf2(kq.y, kf[2], kf[3]);
        unpack_bf2(kq.z, kf[4], kf[5]);
        unpack_bf2(kq.w, kf[6], kf[7]);
        float4 rv0 = *(const float4*)(relb + e);
        float4 rv1 = *(const float4*)(relb + e + 4);
        float ui  = su[i] * 512.f;
        float pai = pa[b*NN + i];
        float4 vv0 = *(const float4*)(sv + j);
        float4 vv1 = *(const float4*)(sv + j + 4);
        float d0 = ui*kf[0]*vv0.x - rv0.x;
        float d1 = ui*kf[1]*vv0.y - rv0.y;
        float d2 = ui*kf[2]*vv0.z - rv0.z;
        float d3 = ui*kf[3]*vv0.w - rv0.w;
        float d4 = ui*kf[4]*vv1.x - rv1.x;
        float d5 = ui*kf[5]*vv1.y - rv1.y;
        float d6 = ui*kf[6]*vv1.z - rv1.z;
        float d7 = ui*kf[7]*vv1.w - rv1.w;
        lacc += pai * (d0*d0 + d1*d1 + d2*d2 + d3*d3
                     + d4*d4 + d5*d5 + d6*d6 + d7*d7);
    }
    #pragma unroll
    for (int off = 16; off; off >>= 1)
        lacc += __shfl_xor_sync(0xffffffffu, lacc, off);
    if (lane == 0) sred[warp] = lacc;
    __syncthreads();
    if (tid == 0) {
        float s = 0.f;
        #pragma unroll
        for (int w = 0; w < 32; w++) s += sred[w];
        atomicAdd(&g_acc[2], (double)s);
    }
}

__global__ void finalize_kernel(const float* __restrict__ pa, float* __restrict__ out)
{
    __shared__ float red[256];
    float s = 0.f;
    for (int i = threadIdx.x; i < BSZ*NN; i += 256) s += pa[i];
    red[threadIdx.x] = s;
    __syncthreads();
    for (int off = 128; off; off >>= 1) {
        if (threadIdx.x < off) red[threadIdx.x] += red[threadIdx.x + off];
        __syncthreads();
    }
    if (threadIdx.x == 0) {
        double M = (double)BSZ * (double)NN * (double)NN;
        out[0] = (float)(g_acc[0]/M - g_acc[1]/M + 10.0*(g_acc[2]/(double)red[0]));
    }
}

extern "C" void kernel_launch(void* const* d_in, const int* in_sizes, int n_in,
                              void* d_out, int out_size)
{
    const float* la  = (const float*)d_in[0];
    const float* lb  = (const float*)d_in[1];
    const float* xA  = (const float*)d_in[2];
    const float* xB  = (const float*)d_in[3];
    const float* rel = (const float*)d_in[4];
    const float* pa  = (const float*)d_in[5];
    const float* pb  = (const float*)d_in[6];
    const float* W1  = (const float*)d_in[7];
    const float* b1  = (const float*)d_in[8];
    const float* g1  = (const float*)d_in[9];
    const float* be1 = (const float*)d_in[10];
    const float* W2  = (const float*)d_in[11];
    const float* b2  = (const float*)d_in[12];
    const float* g2  = (const float*)d_in[13];
    const float* be2 = (const float*)d_in[14];
    float* out = (float*)d_out;

    cudaFuncSetAttribute(embed_kernel,
                         cudaFuncAttributeMaxDynamicSharedMemorySize, EMBED_SMEM);

    zero_acc_kernel<<<1, 32>>>();
    class_argmax_kernel<<<(BSZ*NN + 255)/256, 256>>>(la, lb);
    embed_kernel<<<dim3(BSZ*NN/64, 2), 256, EMBED_SMEM>>>(
        xA, xB, W1, b1, g1, be1, W2, b2, g2, be2);
    cost_kernel<<<dim3(4, 4, BSZ), 256>>>(pa, pb);
    sinkhorn_kernel<<<BSZ, 1024>>>(rel, pa);
    finalize_kernel<<<1, 256>>>(pa, out);
}

// round 9
// speedup vs baseline: 2.4898x; 1.2727x over previous
#include <cuda_runtime.h>
#include <cuda_bf16.h>
#include <stdint.h>
#include <math.h>

#define BSZ 64
#define NN 512
#define DD 256
#define BIGC 1.0e9f

__device__ float g_eA[BSZ*NN*DD];
__device__ float g_eB[BSZ*NN*DD];
__device__ float g_nA[BSZ*NN];
__device__ float g_nB[BSZ*NN];
__device__ __nv_bfloat16 g_K[(size_t)BSZ*NN*NN];
__device__ int   g_cA[BSZ*NN];
__device__ int   g_cB[BSZ*NN];
__device__ double g_acc[3];

// ---- helpers ----
__device__ __forceinline__ uint32_t pack_bf2(float a, float b) {
    __nv_bfloat162 h = __floats2bfloat162_rn(a, b);
    return *reinterpret_cast<uint32_t*>(&h);
}
__device__ __forceinline__ void unpack_bf2(uint32_t u, float& a, float& b) {
    a = __uint_as_float(u << 16);
    b = __uint_as_float(u & 0xffff0000u);
}
__device__ __forceinline__ void cp_async16(void* smem_dst, const void* gmem_src) {
    uint32_t s = (uint32_t)__cvta_generic_to_shared(smem_dst);
    asm volatile("cp.async.cg.shared.global [%0], [%1], 16;" :: "r"(s), "l"(gmem_src));
}
__device__ __forceinline__ void cp_commit() {
    asm volatile("cp.async.commit_group;");
}
__device__ __forceinline__ void cp_wait0() {
    asm volatile("cp.async.wait_group 0;");
}
__device__ __forceinline__ void mma_tf32(float* c,
    uint32_t a0, uint32_t a1, uint32_t a2, uint32_t a3,
    uint32_t b0, uint32_t b1)
{
    asm volatile(
        "mma.sync.aligned.m16n8k8.row.col.f32.tf32.tf32.f32 "
        "{%0,%1,%2,%3}, {%4,%5,%6,%7}, {%8,%9}, {%0,%1,%2,%3};"
        : "+f"(c[0]), "+f"(c[1]), "+f"(c[2]), "+f"(c[3])
        : "r"(a0), "r"(a1), "r"(a2), "r"(a3), "r"(b0), "r"(b1));
}

__global__ void zero_acc_kernel() {
    if (threadIdx.x < 3) g_acc[threadIdx.x] = 0.0;
}

__global__ void class_argmax_kernel(const float* __restrict__ la,
                                    const float* __restrict__ lb) {
    int t = blockIdx.x * blockDim.x + threadIdx.x;
    if (t >= BSZ*NN) return;
    float4 a = ((const float4*)la)[t];
    int ba = 0; float bv = a.x;
    if (a.y > bv) { bv = a.y; ba = 1; }
    if (a.z > bv) { bv = a.z; ba = 2; }
    if (a.w > bv) { bv = a.w; ba = 3; }
    g_cA[t] = ba;
    float4 b = ((const float4*)lb)[t];
    int bb = 0; bv = b.x;
    if (b.y > bv) { bv = b.y; bb = 1; }
    if (b.z > bv) { bv = b.z; bb = 2; }
    if (b.w > bv) { bv = b.w; bb = 3; }
    g_cB[t] = bb;
}

__device__ __forceinline__ void ln_row(float v[8],
    const float4& g0, const float4& g1, const float4& e0, const float4& e1,
    float* o)
{
    float s = 0.f, sq = 0.f;
    #pragma unroll
    for (int j = 0; j < 8; j++) {
        v[j] = v[j] > 0.f ? v[j] : 0.01f * v[j];
        s += v[j]; sq += v[j]*v[j];
    }
    #pragma unroll
    for (int off = 16; off; off >>= 1) {
        s  += __shfl_xor_sync(0xffffffffu, s, off);
        sq += __shfl_xor_sync(0xffffffffu, sq, off);
    }
    float mean = s * (1.f/256.f);
    float var  = sq * (1.f/256.f) - mean*mean;
    float rstd = rsqrtf(var + 1e-5f);
    o[0] = (v[0]-mean)*rstd*g0.x + e0.x;
    o[1] = (v[1]-mean)*rstd*g0.y + e0.y;
    o[2] = (v[2]-mean)*rstd*g0.z + e0.z;
    o[3] = (v[3]-mean)*rstd*g0.w + e0.w;
    o[4] = (v[4]-mean)*rstd*g1.x + e1.x;
    o[5] = (v[5]-mean)*rstd*g1.y + e1.y;
    o[6] = (v[6]-mean)*rstd*g1.z + e1.z;
    o[7] = (v[7]-mean)*rstd*g1.w + e1.w;
}

// Fused 2-layer MLP+LN embed with tf32 mma.sync (unchanged from R8 winner).
#define EMBED_SMEM ((64*256 + 2*16*256 + 2*64*16) * 4)

__global__ __launch_bounds__(256, 2)
void embed_kernel(const float* __restrict__ xA, const float* __restrict__ xB,
                  const float* __restrict__ W1, const float* __restrict__ b1,
                  const float* __restrict__ g1, const float* __restrict__ be1,
                  const float* __restrict__ W2, const float* __restrict__ b2,
                  const float* __restrict__ g2, const float* __restrict__ be2)
{
    extern __shared__ float sm[];
    float* Hs = sm;                  // 64*256 (swizzled)
    float* Ws = sm + 64*256;         // 2 x 16*256 (swizzled)
    float* Xs = Ws + 2*16*256;       // 2 x 64*16 (swizzled)

    const float* X  = blockIdx.y ? xB   : xA;
    float* E        = blockIdx.y ? g_eB : g_eA;
    float* NRM      = blockIdx.y ? g_nB : g_nA;

    const int tid  = threadIdx.x;
    const int lane = tid & 31;
    const int warp = tid >> 5;
    const int wm   = warp & 3;
    const int wn   = warp >> 2;
    const int g    = lane >> 2;
    const int t    = lane & 3;
    const int row0 = blockIdx.x * 64;

    const int xr = tid >> 2, xkq = (tid & 3) << 2;
    const int xdst = xr*16 + (xkq ^ (((xr>>1)&3)<<2));

    float c[16][4];
    #pragma unroll
    for (int j = 0; j < 16; j++)
        #pragma unroll
        for (int q = 0; q < 4; q++) c[j][q] = 0.f;

    {
        #pragma unroll
        for (int i = 0; i < 4; i++) {
            int f = tid + i*256;
            int k = f >> 6, n4 = (f & 63) << 2;
            cp_async16(Ws + k*256 + (n4 ^ ((k&3)<<3)), W1 + (size_t)k*256 + n4);
        }
        cp_async16(Xs + xdst, X + (size_t)(row0 + xr)*DD + xkq);
        cp_commit(); cp_wait0();
    }
    __syncthreads();

    for (int kt = 0; kt < 16; kt++) {
        const int cur = kt & 1, nxt = cur ^ 1;
        if (kt < 15) {
            const float* Wsrc = W1 + (size_t)(kt+1)*16*DD;
            float* Wdst = Ws + nxt*4096;
            #pragma unroll
            for (int i = 0; i < 4; i++) {
                int f = tid + i*256;
                int k = f >> 6, n4 = (f & 63) << 2;
                cp_async16(Wdst + k*256 + (n4 ^ ((k&3)<<3)), Wsrc + (size_t)k*256 + n4);
            }
            cp_async16(Xs + nxt*1024 + xdst,
                       X + (size_t)(row0 + xr)*DD + (kt+1)*16 + xkq);
            cp_commit();
        }
        const float* Wc = Ws + cur*4096;
        const float* Xc = Xs + cur*1024;
        const int sA = ((g>>1)&3) << 2;
        const int sB = t << 3;
        #pragma unroll
        for (int h = 0; h < 2; h++) {
            int kl = h*8 + t;
            uint32_t a0 = __float_as_uint(Xc[(wm*16+g  )*16 + ((kl  ) ^ sA)]);
            uint32_t a1 = __float_as_uint(Xc[(wm*16+g+8)*16 + ((kl  ) ^ sA)]);
            uint32_t a2 = __float_as_uint(Xc[(wm*16+g  )*16 + ((kl+4) ^ sA)]);
            uint32_t a3 = __float_as_uint(Xc[(wm*16+g+8)*16 + ((kl+4) ^ sA)]);
            const float* Wr0 = Wc + (kl  )*256;
            const float* Wr1 = Wc + (kl+4)*256;
            #pragma unroll
            for (int j = 0; j < 16; j++) {
                int n = wn*128 + j*8 + g;
                uint32_t b0 = __float_as_uint(Wr0[n ^ sB]);
                uint32_t b1 = __float_as_uint(Wr1[n ^ sB]);
                mma_tf32(c[j], a0, a1, a2, a3, b0, b1);
            }
        }
        if (kt < 15) cp_wait0();
        __syncthreads();
    }

    {
        #pragma unroll
        for (int i = 0; i < 4; i++) {
            int f = tid + i*256;
            int k = f >> 6, n4 = (f & 63) << 2;
            cp_async16(Ws + k*256 + (n4 ^ ((k&3)<<3)), W2 + (size_t)k*256 + n4);
        }
        cp_commit();
    }

    #pragma unroll
    for (int j = 0; j < 16; j++) {
        int r  = wm*16 + g;
        int cc = wn*128 + j*8 + 2*t;
        *(float2*)&Hs[r*256 + (cc ^ ((r&7)<<2))] = make_float2(c[j][0], c[j][1]);
        int r2 = r + 8;
        *(float2*)&Hs[r2*256 + (cc ^ ((r2&7)<<2))] = make_float2(c[j][2], c[j][3]);
    }
    __syncthreads();

    {
        const int c0 = lane*4, c1 = 128 + lane*4;
        float4 bv0 = *(const float4*)(b1 + c0), bv1 = *(const float4*)(b1 + c1);
        float4 gv0 = *(const float4*)(g1 + c0), gv1 = *(const float4*)(g1 + c1);
        float4 ev0 = *(const float4*)(be1 + c0), ev1 = *(const float4*)(be1 + c1);
        #pragma unroll
        for (int r = 0; r < 8; r++) {
            int row = warp*8 + r;
            int sH = (row & 7) << 2;
            float4 x0 = *(const float4*)&Hs[row*256 + (c0 ^ sH)];
            float4 x1 = *(const float4*)&Hs[row*256 + (c1 ^ sH)];
            float v[8], o[8];
            v[0]=x0.x+bv0.x; v[1]=x0.y+bv0.y; v[2]=x0.z+bv0.z; v[3]=x0.w+bv0.w;
            v[4]=x1.x+bv1.x; v[5]=x1.y+bv1.y; v[6]=x1.z+bv1.z; v[7]=x1.w+bv1.w;
            ln_row(v, gv0, gv1, ev0, ev1, o);
            *(float4*)&Hs[row*256 + (c0 ^ sH)] = make_float4(o[0],o[1],o[2],o[3]);
            *(float4*)&Hs[row*256 + (c1 ^ sH)] = make_float4(o[4],o[5],o[6],o[7]);
        }
    }
    cp_wait0();
    __syncthreads();

    #pragma unroll
    for (int j = 0; j < 16; j++)
        #pragma unroll
        for (int q = 0; q < 4; q++) c[j][q] = 0.f;

    for (int kt = 0; kt < 16; kt++) {
        const int cur = kt & 1, nxt = cur ^ 1;
        if (kt < 15) {
            const float* Wsrc = W2 + (size_t)(kt+1)*16*DD;
            float* Wdst = Ws + nxt*4096;
            #pragma unroll
            for (int i = 0; i < 4; i++) {
                int f = tid + i*256;
                int k = f >> 6, n4 = (f & 63) << 2;
                cp_async16(Wdst + k*256 + (n4 ^ ((k&3)<<3)), Wsrc + (size_t)k*256 + n4);
            }
            cp_commit();
        }
        const float* Wc = Ws + cur*4096;
        const float* H0 = Hs + (wm*16 + g  )*256;
        const float* H1 = Hs + (wm*16 + g+8)*256;
        const int sH = g << 2;
        const int sB = t << 3;
        #pragma unroll
        for (int h = 0; h < 2; h++) {
            int k = kt*16 + h*8;
            uint32_t a0 = __float_as_uint(H0[(k+t  ) ^ sH]);
            uint32_t a1 = __float_as_uint(H1[(k+t  ) ^ sH]);
            uint32_t a2 = __float_as_uint(H0[(k+t+4) ^ sH]);
            uint32_t a3 = __float_as_uint(H1[(k+t+4) ^ sH]);
            const float* Wr0 = Wc + (h*8+t  )*256;
            const float* Wr1 = Wc + (h*8+t+4)*256;
            #pragma unroll
            for (int j = 0; j < 16; j++) {
                int n = wn*128 + j*8 + g;
                uint32_t b0 = __float_as_uint(Wr0[n ^ sB]);
                uint32_t b1 = __float_as_uint(Wr1[n ^ sB]);
                mma_tf32(c[j], a0, a1, a2, a3, b0, b1);
            }
        }
        if (kt < 15) cp_wait0();
        __syncthreads();
    }

    #pragma unroll
    for (int j = 0; j < 16; j++) {
        int r  = wm*16 + g;
        int cc = wn*128 + j*8 + 2*t;
        *(float2*)&Hs[r*256 + (cc ^ ((r&7)<<2))] = make_float2(c[j][0], c[j][1]);
        int r2 = r + 8;
        *(float2*)&Hs[r2*256 + (cc ^ ((r2&7)<<2))] = make_float2(c[j][2], c[j][3]);
    }
    __syncthreads();

    {
        const int c0 = lane*4, c1 = 128 + lane*4;
        float4 bv0 = *(const float4*)(b2 + c0), bv1 = *(const float4*)(b2 + c1);
        float4 gv0 = *(const float4*)(g2 + c0), gv1 = *(const float4*)(g2 + c1);
        float4 ev0 = *(const float4*)(be2 + c0), ev1 = *(const float4*)(be2 + c1);
        #pragma unroll
        for (int r = 0; r < 8; r++) {
            int row = warp*8 + r;
            int sH = (row & 7) << 2;
            float4 x0 = *(const float4*)&Hs[row*256 + (c0 ^ sH)];
            float4 x1 = *(const float4*)&Hs[row*256 + (c1 ^ sH)];
            float v[8], o[8];
            v[0]=x0.x+bv0.x; v[1]=x0.y+bv0.y; v[2]=x0.z+bv0.z; v[3]=x0.w+bv0.w;
            v[4]=x1.x+bv1.x; v[5]=x1.y+bv1.y; v[6]=x1.z+bv1.z; v[7]=x1.w+bv1.w;
            ln_row(v, gv0, gv1, ev0, ev1, o);
            float ns = o[0]*o[0]+o[1]*o[1]+o[2]*o[2]+o[3]*o[3]
                     + o[4]*o[4]+o[5]*o[5]+o[6]*o[6]+o[7]*o[7];
            #pragma unroll
            for (int off = 16; off; off >>= 1)
                ns += __shfl_xor_sync(0xffffffffu, ns, off);
            size_t grow = (size_t)(row0 + row);
            *(float4*)(E + grow*DD + c0) = make_float4(o[0],o[1],o[2],o[3]);
            *(float4*)(E + grow*DD + c1) = make_float4(o[4],o[5],o[6],o[7]);
            if (lane == 0) NRM[grow] = ns;
        }
    }
}

// cdist + cost_class + in/out loss + K(bf16) via tf32 mma.sync.
// 128x128 tile, 8 warps (4x2), warp tile 32x64, cp.async double-buffered.
// Smem tiles [128 rows][16 k], swizzle (r,k) -> k ^ (((r>>1)&3)<<2).
__global__ __launch_bounds__(256, 2)
void cost_kernel(const float* __restrict__ pa, const float* __restrict__ pb)
{
    __shared__ __align__(16) float As[2][128*16];
    __shared__ __align__(16) float Bs[2][128*16];
    __shared__ float redi[8], redo[8];

    const int b  = blockIdx.z;
    const int ti = blockIdx.y;
    const int tj = blockIdx.x;
    const int tid = threadIdx.x;
    const int lane = tid & 31;
    const int warp = tid >> 5;
    const int wm   = warp & 3;      // row group: rows wm*32..+31
    const int wn   = warp >> 2;     // col group: cols wn*64..+63
    const int g    = lane >> 2;
    const int t    = lane & 3;

    const float* Ab = g_eA + (size_t)b*NN*DD + (size_t)ti*128*DD;
    const float* Bb = g_eB + (size_t)b*NN*DD + (size_t)tj*128*DD;

    // loader: f = tid + i*256 (i=0,1) -> row = f>>2, kq = (f&3)<<2
    const int lr  = tid >> 2;
    const int lkq = (tid & 3) << 2;

    float c[2][8][4];
    #pragma unroll
    for (int m = 0; m < 2; m++)
        #pragma unroll
        for (int j = 0; j < 8; j++)
            #pragma unroll
            for (int q = 0; q < 4; q++) c[m][j][q] = 0.f;

    {   // prologue: kt=0 -> buf 0
        #pragma unroll
        for (int i = 0; i < 2; i++) {
            int row = lr + i*64;
            int dst = row*16 + (lkq ^ (((row>>1)&3)<<2));
            cp_async16(&As[0][dst], Ab + (size_t)row*DD + lkq);
            cp_async16(&Bs[0][dst], Bb + (size_t)row*DD + lkq);
        }
        cp_commit(); cp_wait0();
    }
    __syncthreads();

    const int sA = ((g>>1)&3) << 2;

    for (int kt = 0; kt < 16; kt++) {
        const int cur = kt & 1, nxt = cur ^ 1;
        if (kt < 15) {
            #pragma unroll
            for (int i = 0; i < 2; i++) {
                int row = lr + i*64;
                int dst = row*16 + (lkq ^ (((row>>1)&3)<<2));
                cp_async16(&As[nxt][dst], Ab + (size_t)row*DD + (kt+1)*16 + lkq);
                cp_async16(&Bs[nxt][dst], Bb + (size_t)row*DD + (kt+1)*16 + lkq);
            }
            cp_commit();
        }
        const float* Ac = As[cur];
        const float* Bc = Bs[cur];
        #pragma unroll
        for (int h = 0; h < 2; h++) {
            int kl = h*8 + t;
            #pragma unroll
            for (int m = 0; m < 2; m++) {
                int r = wm*32 + m*16 + g;
                uint32_t a0 = __float_as_uint(Ac[(r  )*16 + ((kl  ) ^ sA)]);
                uint32_t a1 = __float_as_uint(Ac[(r+8)*16 + ((kl  ) ^ sA)]);
                uint32_t a2 = __float_as_uint(Ac[(r  )*16 + ((kl+4) ^ sA)]);
                uint32_t a3 = __float_as_uint(Ac[(r+8)*16 + ((kl+4) ^ sA)]);
                #pragma unroll
                for (int j = 0; j < 8; j++) {
                    int n = wn*64 + j*8 + g;
                    uint32_t b0 = __float_as_uint(Bc[n*16 + ((kl  ) ^ sA)]);
                    uint32_t b1 = __float_as_uint(Bc[n*16 + ((kl+4) ^ sA)]);
                    mma_tf32(c[m][j], a0, a1, a2, a3, b0, b1);
                }
            }
        }
        if (kt < 15) cp_wait0();
        __syncthreads();
    }

    // epilogue directly from fragments:
    // c[m][j][0..1] -> row r1 = wm*32+m*16+g, cols cc, cc+1
    // c[m][j][2..3] -> row r2 = r1+8
    float sin = 0.f, sout = 0.f;
    #pragma unroll
    for (int m = 0; m < 2; m++) {
        int il1 = ti*128 + wm*32 + m*16 + g;
        int il2 = il1 + 8;
        int gi1 = b*NN + il1, gi2 = b*NN + il2;
        float ni1 = g_nA[gi1], ni2 = g_nA[gi2];
        float pa1 = pa[gi1],   pa2 = pa[gi2];
        int   ca1 = g_cA[gi1], ca2 = g_cA[gi2];
        size_t rb1 = (size_t)gi1 * NN;
        size_t rb2 = (size_t)gi2 * NN;
        #pragma unroll
        for (int j = 0; j < 8; j++) {
            int jl = tj*128 + wn*64 + j*8 + 2*t;
            int gj = b*NN + jl;
            float nj0 = g_nB[gj], nj1 = g_nB[gj+1];
            float pb0 = pb[gj],   pb1 = pb[gj+1];
            int   cb0 = g_cB[gj], cb1 = g_cB[gj+1];

            float sq, cost, pm, cc, w;
            float k00, k01, k10, k11;

            sq = ni1 + nj0 - 2.f*c[m][j][0];
            cost = sqrtf(fmaxf(sq, 0.f));
            pm = pa1*pb0; cc = cost + (BIGC - BIGC*pm); w = cc*pm;
            if (ca1 == cb0) sin += w; else sout += w;
            k00 = __expf(-2.f*cc);

            sq = ni1 + nj1 - 2.f*c[m][j][1];
            cost = sqrtf(fmaxf(sq, 0.f));
            pm = pa1*pb1; cc = cost + (BIGC - BIGC*pm); w = cc*pm;
            if (ca1 == cb1) sin += w; else sout += w;
            k01 = __expf(-2.f*cc);

            sq = ni2 + nj0 - 2.f*c[m][j][2];
            cost = sqrtf(fmaxf(sq, 0.f));
            pm = pa2*pb0; cc = cost + (BIGC - BIGC*pm); w = cc*pm;
            if (ca2 == cb0) sin += w; else sout += w;
            k10 = __expf(-2.f*cc);

            sq = ni2 + nj1 - 2.f*c[m][j][3];
            cost = sqrtf(fmaxf(sq, 0.f));
            pm = pa2*pb1; cc = cost + (BIGC - BIGC*pm); w = cc*pm;
            if (ca2 == cb1) sin += w; else sout += w;
            k11 = __expf(-2.f*cc);

            *(uint32_t*)(g_K + rb1 + jl) = pack_bf2(k00, k01);
            *(uint32_t*)(g_K + rb2 + jl) = pack_bf2(k10, k11);
        }
    }
    #pragma unroll
    for (int off = 16; off; off >>= 1) {
        sin  += __shfl_xor_sync(0xffffffffu, sin,  off);
        sout += __shfl_xor_sync(0xffffffffu, sout, off);
    }
    if (lane == 0) { redi[warp] = sin; redo[warp] = sout; }
    __syncthreads();
    if (tid == 0) {
        float a = 0.f, o2 = 0.f;
        #pragma unroll
        for (int w = 0; w < 8; w++) { a += redi[w]; o2 += redo[w]; }
        atomicAdd(&g_acc[0], (double)a);
        atomicAdd(&g_acc[1], (double)o2);
    }
}

// Sinkhorn + fused sup loss. 1 CTA (1024 threads) per batch (unchanged).
__global__ __launch_bounds__(1024)
void sinkhorn_kernel(const float* __restrict__ rel, const float* __restrict__ pa)
{
    __shared__ __align__(16) float su[NN];
    __shared__ __align__(16) float sv[NN];
    __shared__ __align__(16) float part[8][NN];
    __shared__ float sred[32];

    const int b = blockIdx.x;
    const __nv_bfloat16* Kb = g_K + (size_t)b*NN*NN;
    const int tid  = threadIdx.x;
    const int lane = tid & 31;
    const int warp = tid >> 5;
    const int grp  = tid >> 7;
    const int jc   = (tid & 127) * 4;

    if (tid < NN) su[tid] = 1.f/512.f;
    __syncthreads();

    for (int it = 0; it < 10; it++) {
        float a0 = 0.f, a1 = 0.f, a2 = 0.f, a3 = 0.f;
        const int i0 = grp * 64;
        const uint2* K2 = (const uint2*)Kb;
        #pragma unroll 8
        for (int i = 0; i < 64; i++) {
            uint2 kq = K2[(((size_t)(i0 + i))*NN + jc) >> 2];
            float k0,k1,k2,k3;
            unpack_bf2(kq.x, k0, k1);
            unpack_bf2(kq.y, k2, k3);
            float ui = su[i0 + i];
            a0 = fmaf(k0, ui, a0);
            a1 = fmaf(k1, ui, a1);
            a2 = fmaf(k2, ui, a2);
            a3 = fmaf(k3, ui, a3);
        }
        *(float4*)(&part[grp][jc]) = make_float4(a0,a1,a2,a3);
        __syncthreads();
        if (tid < NN) {
            float y = part[0][tid] + part[1][tid] + part[2][tid] + part[3][tid]
                    + part[4][tid] + part[5][tid] + part[6][tid] + part[7][tid];
            sv[tid] = (1.f/512.f) / y;
        }
        __syncthreads();
        for (int rr = 0; rr < 16; rr++) {
            int i = warp*16 + rr;
            const uint4* kr = (const uint4*)(Kb + (size_t)i*NN);
            uint4 q0 = kr[lane*2];
            uint4 q1 = kr[lane*2 + 1];
            float s = 0.f;
            float k0,k1;
            float4 vv;
            vv = *(const float4*)(sv + lane*16 + 0);
            unpack_bf2(q0.x, k0, k1); s = fmaf(k0, vv.x, s); s = fmaf(k1, vv.y, s);
            unpack_bf2(q0.y, k0, k1); s = fmaf(k0, vv.z, s); s = fmaf(k1, vv.w, s);
            vv = *(const float4*)(sv + lane*16 + 4);
            unpack_bf2(q0.z, k0, k1); s = fmaf(k0, vv.x, s); s = fmaf(k1, vv.y, s);
            unpack_bf2(q0.w, k0, k1); s = fmaf(k0, vv.z, s); s = fmaf(k1, vv.w, s);
            vv = *(const float4*)(sv + lane*16 + 8);
            unpack_bf2(q1.x, k0, k1); s = fmaf(k0, vv.x, s); s = fmaf(k1, vv.y, s);
            unpack_bf2(q1.y, k0, k1); s = fmaf(k0, vv.z, s); s = fmaf(k1, vv.w, s);
            vv = *(const float4*)(sv + lane*16 + 12);
            unpack_bf2(q1.z, k0, k1); s = fmaf(k0, vv.x, s); s = fmaf(k1, vv.y, s);
            unpack_bf2(q1.w, k0, k1); s = fmaf(k0, vv.z, s); s = fmaf(k1, vv.w, s);
            #pragma unroll
            for (int off = 16; off; off >>= 1)
                s += __shfl_xor_sync(0xffffffffu, s, off);
            if (lane == 0) su[i] = (1.f/512.f) / s;
        }
        __syncthreads();
    }

    const float* relb = rel + (size_t)b*NN*NN;
    float lacc = 0.f;
    for (int t = 0; t < 32; t++) {
        int idx = tid + t*1024;
        int e = idx * 8;
        int i = e >> 9;
        int j = e & 511;
        uint4 kq = ((const uint4*)Kb)[idx];
        float kf[8];
        unpack_bf2(kq.x, kf[0], kf[1]);
        unpack_bf2(kq.y, kf[2], kf[3]);
        unpack_bf2(kq.z, kf[4], kf[5]);
        unpack_bf2(kq.w, kf[6], kf[7]);
        float4 rv0 = *(const float4*)(relb + e);
        float4 rv1 = *(const float4*)(relb + e + 4);
        float ui  = su[i] * 512.f;
        float pai = pa[b*NN + i];
        float4 vv0 = *(const float4*)(sv + j);
        float4 vv1 = *(const float4*)(sv + j + 4);
        float d0 = ui*kf[0]*vv0.x - rv0.x;
        float d1 = ui*kf[1]*vv0.y - rv0.y;
        float d2 = ui*kf[2]*vv0.z - rv0.z;
        float d3 = ui*kf[3]*vv0.w - rv0.w;
        float d4 = ui*kf[4]*vv1.x - rv1.x;
        float d5 = ui*kf[5]*vv1.y - rv1.y;
        float d6 = ui*kf[6]*vv1.z - rv1.z;
        float d7 = ui*kf[7]*vv1.w - rv1.w;
        lacc += pai * (d0*d0 + d1*d1 + d2*d2 + d3*d3
                     + d4*d4 + d5*d5 + d6*d6 + d7*d7);
    }
    #pragma unroll
    for (int off = 16; off; off >>= 1)
        lacc += __shfl_xor_sync(0xffffffffu, lacc, off);
    if (lane == 0) sred[warp] = lacc;
    __syncthreads();
    if (tid == 0) {
        float s = 0.f;
        #pragma unroll
        for (int w = 0; w < 32; w++) s += sred[w];
        atomicAdd(&g_acc[2], (double)s);
    }
}

__global__ void finalize_kernel(const float* __restrict__ pa, float* __restrict__ out)
{
    __shared__ float red[256];
    float s = 0.f;
    for (int i = threadIdx.x; i < BSZ*NN; i += 256) s += pa[i];
    red[threadIdx.x] = s;
    __syncthreads();
    for (int off = 128; off; off >>= 1) {
        if (threadIdx.x < off) red[threadIdx.x] += red[threadIdx.x + off];
        __syncthreads();
    }
    if (threadIdx.x == 0) {
        double M = (double)BSZ * (double)NN * (double)NN;
        out[0] = (float)(g_acc[0]/M - g_acc[1]/M + 10.0*(g_acc[2]/(double)red[0]));
    }
}

extern "C" void kernel_launch(void* const* d_in, const int* in_sizes, int n_in,
                              void* d_out, int out_size)
{
    const float* la  = (const float*)d_in[0];
    const float* lb  = (const float*)d_in[1];
    const float* xA  = (const float*)d_in[2];
    const float* xB  = (const float*)d_in[3];
    const float* rel = (const float*)d_in[4];
    const float* pa  = (const float*)d_in[5];
    const float* pb  = (const float*)d_in[6];
    const float* W1  = (const float*)d_in[7];
    const float* b1  = (const float*)d_in[8];
    const float* g1  = (const float*)d_in[9];
    const float* be1 = (const float*)d_in[10];
    const float* W2  = (const float*)d_in[11];
    const float* b2  = (const float*)d_in[12];
    const float* g2  = (const float*)d_in[13];
    const float* be2 = (const float*)d_in[14];
    float* out = (float*)d_out;

    cudaFuncSetAttribute(embed_kernel,
                         cudaFuncAttributeMaxDynamicSharedMemorySize, EMBED_SMEM);

    zero_acc_kernel<<<1, 32>>>();
    class_argmax_kernel<<<(BSZ*NN + 255)/256, 256>>>(la, lb);
    embed_kernel<<<dim3(BSZ*NN/64, 2), 256, EMBED_SMEM>>>(
        xA, xB, W1, b1, g1, be1, W2, b2, g2, be2);
    cost_kernel<<<dim3(4, 4, BSZ), 256>>>(pa, pb);
    sinkhorn_kernel<<<BSZ, 1024>>>(rel, pa);
    finalize_kernel<<<1, 256>>>(pa, out);
}